// round 11
// baseline (speedup 1.0000x reference)
#include <cuda_runtime.h>
#include <cuda_bf16.h>
#include <math.h>

#define S    2048
#define NH   32
#define HD   128
#define HID  4096
#define NEGV -1000000000.0f
#define HHSZ 204
#define RECENT 204
#define SEL  (S - RECENT)

typedef __nv_bfloat16 bf16;

// ---------------- scratch ----------------------------------------------------
__device__ float g_q[(size_t)S * HID];
__device__ float g_k[(size_t)S * HID];
__device__ float g_scores[(size_t)NH * S * S];
__device__ float g_hh[NH * S];
__device__ float g_hhpart[8 * NH * S];
__device__ float g_mask[NH * S];

__device__ bf16 g_hs_b[(size_t)S * HID],  g_hs_s[(size_t)S * HID];
__device__ bf16 g_w_b[4][(size_t)HID * HID], g_w_s[4][(size_t)HID * HID];
__device__ bf16 g_qb[(size_t)S * HID], g_qs[(size_t)S * HID];
__device__ bf16 g_kb[(size_t)S * HID], g_ks[(size_t)S * HID];
__device__ bf16 g_vb[(size_t)S * HID], g_vs[(size_t)S * HID];
__device__ bf16 g_pb[(size_t)NH * S * S], g_ps[(size_t)NH * S * S];
__device__ bf16 g_ab[(size_t)S * HID], g_as[(size_t)S * HID];

// ---------------- HMMA helpers (proven) --------------------------------------
__device__ __forceinline__ void mma_bf16(float c[4],
    unsigned a0, unsigned a1, unsigned a2, unsigned a3, unsigned b0, unsigned b1)
{
    asm volatile(
        "mma.sync.aligned.m16n8k16.row.col.f32.bf16.bf16.f32 "
        "{%0,%1,%2,%3}, {%4,%5,%6,%7}, {%8,%9}, {%0,%1,%2,%3};"
        : "+f"(c[0]), "+f"(c[1]), "+f"(c[2]), "+f"(c[3])
        : "r"(a0), "r"(a1), "r"(a2), "r"(a3), "r"(b0), "r"(b1));
}
__device__ __forceinline__ void ldsm_x4(unsigned r[4], unsigned addr)
{
    asm volatile("ldmatrix.sync.aligned.m8n8.x4.shared.b16 {%0,%1,%2,%3}, [%4];"
        : "=r"(r[0]), "=r"(r[1]), "=r"(r[2]), "=r"(r[3]) : "r"(addr));
}
__device__ __forceinline__ void ldsm_x4t(unsigned r[4], unsigned addr)
{
    asm volatile("ldmatrix.sync.aligned.m8n8.x4.trans.shared.b16 {%0,%1,%2,%3}, [%4];"
        : "=r"(r[0]), "=r"(r[1]), "=r"(r[2]), "=r"(r[3]) : "r"(addr));
}
__device__ __forceinline__ void cp16(unsigned dst, const void* src)
{
    asm volatile("cp.async.cg.shared.global [%0], [%1], 16;" :: "r"(dst), "l"(src));
}
__device__ __forceinline__ void cp_commit() { asm volatile("cp.async.commit_group;" ::: "memory"); }
__device__ __forceinline__ void cp_wait1() { asm volatile("cp.async.wait_group 1;" ::: "memory"); }
__device__ __forceinline__ void cp_wait0() { asm volatile("cp.async.wait_group 0;" ::: "memory"); }

// term-major MMA issue for one nj: dependent MMAs are 4 apart.
#define MMA_NJ_BLOCK(accA, accB, accA2, accB2, abf, asf, bbf, bsf) do { \
    mma_bf16(accA,  (abf)[0][0], (abf)[0][1], (abf)[0][2], (abf)[0][3], (bsf)[0], (bsf)[1]); \
    mma_bf16(accB,  (abf)[0][0], (abf)[0][1], (abf)[0][2], (abf)[0][3], (bsf)[2], (bsf)[3]); \
    mma_bf16(accA2, (abf)[1][0], (abf)[1][1], (abf)[1][2], (abf)[1][3], (bsf)[0], (bsf)[1]); \
    mma_bf16(accB2, (abf)[1][0], (abf)[1][1], (abf)[1][2], (abf)[1][3], (bsf)[2], (bsf)[3]); \
    mma_bf16(accA,  (asf)[0][0], (asf)[0][1], (asf)[0][2], (asf)[0][3], (bbf)[0], (bbf)[1]); \
    mma_bf16(accB,  (asf)[0][0], (asf)[0][1], (asf)[0][2], (asf)[0][3], (bbf)[2], (bbf)[3]); \
    mma_bf16(accA2, (asf)[1][0], (asf)[1][1], (asf)[1][2], (asf)[1][3], (bbf)[0], (bbf)[1]); \
    mma_bf16(accB2, (asf)[1][0], (asf)[1][1], (asf)[1][2], (asf)[1][3], (bbf)[2], (bbf)[3]); \
    mma_bf16(accA,  (abf)[0][0], (abf)[0][1], (abf)[0][2], (abf)[0][3], (bbf)[0], (bbf)[1]); \
    mma_bf16(accB,  (abf)[0][0], (abf)[0][1], (abf)[0][2], (abf)[0][3], (bbf)[2], (bbf)[3]); \
    mma_bf16(accA2, (abf)[1][0], (abf)[1][1], (abf)[1][2], (abf)[1][3], (bbf)[0], (bbf)[1]); \
    mma_bf16(accB2, (abf)[1][0], (abf)[1][1], (abf)[1][2], (abf)[1][3], (bbf)[2], (bbf)[3]); \
} while (0)

// ================= big-M HMMA GEMM: 256x128 tile, 512 threads, NT ============
#define GB_AST 20
#define GB_ASZ (256 * GB_AST)
#define GB_BSZ (128 * GB_AST)
#define GB_STG (2 * GB_ASZ + 2 * GB_BSZ)
#define GB_SMEM (2 * GB_STG * 4)

template <int EPI>
__global__ __launch_bounds__(512, 1) void gemm_big(
    const bf16* __restrict__ Agb, const bf16* __restrict__ Ags, int lda,
    const bf16* __restrict__ Bgb, const bf16* __restrict__ Bgs, int ldb,
    float* __restrict__ Cf, bf16* __restrict__ Cb, bf16* __restrict__ Cs,
    int ldc, int K)
{
    const int bm = blockIdx.y * 256;
    const int bn = blockIdx.x * 128;
    const int tid  = threadIdx.x;
    const int wid  = tid >> 5;
    const int lane = tid & 31;
    const int g  = lane >> 2;
    const int tg = lane & 3;
    const int wm = (wid & 7) * 32;
    const int wn = (wid >> 3) * 64;

    extern __shared__ unsigned sm[];
    const unsigned smb = (unsigned)__cvta_generic_to_shared(sm);
    const int OFF_AB = 0, OFF_AS = GB_ASZ, OFF_BB = 2 * GB_ASZ, OFF_BS = 2 * GB_ASZ + GB_BSZ;

    const int T = K / 32;

    float acc[2][8][4];
#pragma unroll
    for (int i = 0; i < 2; i++)
#pragma unroll
        for (int j = 0; j < 8; j++)
#pragma unroll
            for (int t2 = 0; t2 < 4; t2++) acc[i][j][t2] = 0.f;

    const int a_row = (lane & 15);
    const int a_hi  = (lane >> 4) << 2;
    const int bnt_row = (lane & 7) + ((lane >> 4) & 1) * 8;
    const int bnt_hi  = ((lane >> 3) & 1) * 4;

    {
        const int so = 0;
#pragma unroll
        for (int r = 0; r < 2; r++) {
            int s = tid + r * 512;
            int arow = s >> 2, aseg = s & 3;
            size_t aoff = (size_t)(bm + arow) * lda + aseg * 8;
            unsigned adst = smb + (so + OFF_AB + arow * GB_AST + aseg * 4) * 4;
            cp16(adst, Agb + aoff);
            cp16(adst + GB_ASZ * 4, Ags + aoff);
        }
        int brow = tid >> 2, bseg = tid & 3;
        size_t boff = (size_t)(bn + brow) * ldb + bseg * 8;
        unsigned bdst = smb + (so + OFF_BB + brow * GB_AST + bseg * 4) * 4;
        cp16(bdst, Bgb + boff);
        cp16(bdst + GB_BSZ * 4, Bgs + boff);
        cp_commit();
    }

    for (int t = 0; t < T; t++) {
        if (t + 1 < T) {
            const int so = ((t + 1) & 1) * GB_STG;
            const int k0 = (t + 1) * 32;
#pragma unroll
            for (int r = 0; r < 2; r++) {
                int s = tid + r * 512;
                int arow = s >> 2, aseg = s & 3;
                size_t aoff = (size_t)(bm + arow) * lda + k0 + aseg * 8;
                unsigned adst = smb + (so + OFF_AB + arow * GB_AST + aseg * 4) * 4;
                cp16(adst, Agb + aoff);
                cp16(adst + GB_ASZ * 4, Ags + aoff);
            }
            int brow = tid >> 2, bseg = tid & 3;
            size_t boff = (size_t)(bn + brow) * ldb + k0 + bseg * 8;
            unsigned bdst = smb + (so + OFF_BB + brow * GB_AST + bseg * 4) * 4;
            cp16(bdst, Bgb + boff);
            cp16(bdst + GB_BSZ * 4, Bgs + boff);
            cp_commit();
            cp_wait1();
        } else {
            cp_wait0();
        }
        __syncthreads();

        const int so = (t & 1) * GB_STG;
#pragma unroll
        for (int kk = 0; kk < 2; kk++) {
            unsigned ab[2][4], as_[2][4];
#pragma unroll
            for (int mi = 0; mi < 2; mi++) {
                int idx = (wm + mi * 16 + a_row) * GB_AST + kk * 8 + a_hi;
                ldsm_x4(ab[mi],  smb + (so + OFF_AB + idx) * 4);
                ldsm_x4(as_[mi], smb + (so + OFF_AS + idx) * 4);
            }
#pragma unroll
            for (int nj = 0; nj < 4; nj++) {
                unsigned bb[4], bs[4];
                int idx = (wn + nj * 16 + bnt_row) * GB_AST + kk * 8 + bnt_hi;
                ldsm_x4(bb, smb + (so + OFF_BB + idx) * 4);
                ldsm_x4(bs, smb + (so + OFF_BS + idx) * 4);
                MMA_NJ_BLOCK(acc[0][2 * nj], acc[0][2 * nj + 1],
                             acc[1][2 * nj], acc[1][2 * nj + 1], ab, as_, bb, bs);
            }
        }
        __syncthreads();
    }

#pragma unroll
    for (int mi = 0; mi < 2; mi++) {
#pragma unroll
        for (int ni = 0; ni < 8; ni++) {
            int r0 = bm + wm + mi * 16 + g;
            int c0 = bn + wn + ni * 8 + tg * 2;
            float v0 = acc[mi][ni][0];
            float v1 = acc[mi][ni][1];
            float v2 = acc[mi][ni][2];
            float v3 = acc[mi][ni][3];
            if (EPI == 2) {
                bf16 b0 = __float2bfloat16(v0), b1 = __float2bfloat16(v1);
                bf16 b2 = __float2bfloat16(v2), b3 = __float2bfloat16(v3);
                __nv_bfloat162 pb0, pb1, ps0, ps1;
                pb0.x = b0; pb0.y = b1; pb1.x = b2; pb1.y = b3;
                ps0.x = __float2bfloat16(v0 - __bfloat162float(b0));
                ps0.y = __float2bfloat16(v1 - __bfloat162float(b1));
                ps1.x = __float2bfloat16(v2 - __bfloat162float(b2));
                ps1.y = __float2bfloat16(v3 - __bfloat162float(b3));
                *(__nv_bfloat162*)(Cb + (size_t)r0 * ldc + c0)       = pb0;
                *(__nv_bfloat162*)(Cb + (size_t)(r0 + 8) * ldc + c0) = pb1;
                *(__nv_bfloat162*)(Cs + (size_t)r0 * ldc + c0)       = ps0;
                *(__nv_bfloat162*)(Cs + (size_t)(r0 + 8) * ldc + c0) = ps1;
            } else {
                *(float2*)(Cf + (size_t)r0 * ldc + c0)       = make_float2(v0, v1);
                *(float2*)(Cf + (size_t)(r0 + 8) * ldc + c0) = make_float2(v2, v3);
            }
        }
    }
}

// ================= HMMA bf16x3 GEMM 128x128 (QK lower-tri / PV) ==============
#define BM 128
#define BN 128
#define BK 32
#define A_ST 20
#define ASZ  (128 * A_ST)
#define BNT_ST 20
#define BNN_ST 68

template <bool NT, int EPI, bool TRUNC, bool LOWER>
__global__ __launch_bounds__(256, 2) void gemm_bf3(
    const bf16* __restrict__ Agb, const bf16* __restrict__ Ags, int lda, size_t sA,
    const bf16* __restrict__ Bgb, const bf16* __restrict__ Bgs, int ldb, size_t sB,
    float* __restrict__ Cf, bf16* __restrict__ Cb, bf16* __restrict__ Cs,
    int ldc, size_t sC, int K, float alpha)
{
    const int bz = blockIdx.z;
    Agb += (size_t)bz * sA; Ags += (size_t)bz * sA;
    Bgb += (size_t)bz * sB; Bgs += (size_t)bz * sB;
    if (EPI == 2) { Cb += (size_t)bz * sC; Cs += (size_t)bz * sC; }
    else          { Cf += (size_t)bz * sC; }

    int bm, bn;
    if (LOWER) {
        int idx = blockIdx.x;
        int r = (int)((sqrtf(8.f * (float)idx + 1.f) - 1.f) * 0.5f);
        while ((r + 1) * (r + 2) / 2 <= idx) r++;
        while (r * (r + 1) / 2 > idx) r--;
        bm = r * BM;
        bn = (idx - r * (r + 1) / 2) * BN;
    } else if (TRUNC) {
        bm = (gridDim.y - 1 - blockIdx.y) * BM;
        bn = blockIdx.x * BN;
    } else {
        bm = blockIdx.y * BM;
        bn = blockIdx.x * BN;
    }

    const int tid  = threadIdx.x;
    const int wid  = tid >> 5;
    const int lane = tid & 31;
    const int g  = lane >> 2;
    const int tg = lane & 3;
    const int wm = (wid & 3) * 32;
    const int wn = (wid >> 2) * 64;

    extern __shared__ unsigned sm[];
    const unsigned smb = (unsigned)__cvta_generic_to_shared(sm);
    const int BSZ = NT ? (128 * BNT_ST) : (32 * BNN_ST);
    const int STG = 2 * ASZ + 2 * BSZ;
    const int OFF_AB = 0, OFF_AS = ASZ, OFF_BB = 2 * ASZ, OFF_BS = 2 * ASZ + BSZ;

    const int kend = TRUNC ? (bm + BM) : K;
    const int T = kend / BK;

    float acc[2][8][4];
#pragma unroll
    for (int i = 0; i < 2; i++)
#pragma unroll
        for (int j = 0; j < 8; j++)
#pragma unroll
            for (int t2 = 0; t2 < 4; t2++) acc[i][j][t2] = 0.f;

    const int a_row = (lane & 15);
    const int a_hi  = (lane >> 4) << 2;
    const int bnt_row = (lane & 7) + ((lane >> 4) & 1) * 8;
    const int bnt_hi  = ((lane >> 3) & 1) * 4;
    const int bnn_krow = (lane & 15);
    const int bnn_nhi  = ((lane >> 4) & 1) * 8;

    {
        const int so = 0;
#pragma unroll
        for (int r = 0; r < 2; r++) {
            int s = tid + r * 256;
            int arow = s >> 2, aseg = s & 3;
            size_t aoff = (size_t)(bm + arow) * lda + aseg * 8;
            unsigned adst = smb + (so + OFF_AB + arow * A_ST + aseg * 4) * 4;
            cp16(adst, Agb + aoff);
            cp16(adst + ASZ * 4, Ags + aoff);
            if (NT) {
                size_t boff = (size_t)(bn + arow) * ldb + aseg * 8;
                unsigned bdst = smb + (so + OFF_BB + arow * BNT_ST + aseg * 4) * 4;
                cp16(bdst, Bgb + boff);
                cp16(bdst + BSZ * 4, Bgs + boff);
            } else {
                int krow = s >> 4, nseg = s & 15;
                size_t boff = (size_t)krow * ldb + bn + nseg * 8;
                unsigned bdst = smb + (so + OFF_BB + krow * BNN_ST + nseg * 4) * 4;
                cp16(bdst, Bgb + boff);
                cp16(bdst + BSZ * 4, Bgs + boff);
            }
        }
        cp_commit();
    }

    for (int t = 0; t < T; t++) {
        if (t + 1 < T) {
            const int so = ((t + 1) & 1) * STG;
            const int k0 = (t + 1) * BK;
#pragma unroll
            for (int r = 0; r < 2; r++) {
                int s = tid + r * 256;
                int arow = s >> 2, aseg = s & 3;
                size_t aoff = (size_t)(bm + arow) * lda + k0 + aseg * 8;
                unsigned adst = smb + (so + OFF_AB + arow * A_ST + aseg * 4) * 4;
                cp16(adst, Agb + aoff);
                cp16(adst + ASZ * 4, Ags + aoff);
                if (NT) {
                    size_t boff = (size_t)(bn + arow) * ldb + k0 + aseg * 8;
                    unsigned bdst = smb + (so + OFF_BB + arow * BNT_ST + aseg * 4) * 4;
                    cp16(bdst, Bgb + boff);
                    cp16(bdst + BSZ * 4, Bgs + boff);
                } else {
                    int krow = s >> 4, nseg = s & 15;
                    size_t boff = (size_t)(k0 + krow) * ldb + bn + nseg * 8;
                    unsigned bdst = smb + (so + OFF_BB + krow * BNN_ST + nseg * 4) * 4;
                    cp16(bdst, Bgb + boff);
                    cp16(bdst + BSZ * 4, Bgs + boff);
                }
            }
            cp_commit();
            cp_wait1();
        } else {
            cp_wait0();
        }
        __syncthreads();

        const int so = (t & 1) * STG;
#pragma unroll
        for (int kk = 0; kk < 2; kk++) {
            unsigned ab[2][4], as_[2][4];
#pragma unroll
            for (int mi = 0; mi < 2; mi++) {
                int idx = (wm + mi * 16 + a_row) * A_ST + kk * 8 + a_hi;
                ldsm_x4(ab[mi],  smb + (so + OFF_AB + idx) * 4);
                ldsm_x4(as_[mi], smb + (so + OFF_AS + idx) * 4);
            }
#pragma unroll
            for (int nj = 0; nj < 4; nj++) {
                unsigned bb[4], bs[4];
                if (NT) {
                    int idx = (wn + nj * 16 + bnt_row) * BNT_ST + kk * 8 + bnt_hi;
                    ldsm_x4(bb, smb + (so + OFF_BB + idx) * 4);
                    ldsm_x4(bs, smb + (so + OFF_BS + idx) * 4);
                } else {
                    int idx = (kk * 16 + bnn_krow) * BNN_ST + ((wn + nj * 16 + bnn_nhi) >> 1);
                    ldsm_x4t(bb, smb + (so + OFF_BB + idx) * 4);
                    ldsm_x4t(bs, smb + (so + OFF_BS + idx) * 4);
                }
                MMA_NJ_BLOCK(acc[0][2 * nj], acc[0][2 * nj + 1],
                             acc[1][2 * nj], acc[1][2 * nj + 1], ab, as_, bb, bs);
            }
        }
        __syncthreads();
    }

#pragma unroll
    for (int mi = 0; mi < 2; mi++) {
#pragma unroll
        for (int ni = 0; ni < 8; ni++) {
            int r0 = bm + wm + mi * 16 + g;
            int c0 = bn + wn + ni * 8 + tg * 2;
            float v0 = acc[mi][ni][0] * alpha;
            float v1 = acc[mi][ni][1] * alpha;
            float v2 = acc[mi][ni][2] * alpha;
            float v3 = acc[mi][ni][3] * alpha;
            if (EPI == 2) {
                bf16 b0 = __float2bfloat16(v0), b1 = __float2bfloat16(v1);
                bf16 b2 = __float2bfloat16(v2), b3 = __float2bfloat16(v3);
                __nv_bfloat162 pb0, pb1, ps0, ps1;
                pb0.x = b0; pb0.y = b1; pb1.x = b2; pb1.y = b3;
                ps0.x = __float2bfloat16(v0 - __bfloat162float(b0));
                ps0.y = __float2bfloat16(v1 - __bfloat162float(b1));
                ps1.x = __float2bfloat16(v2 - __bfloat162float(b2));
                ps1.y = __float2bfloat16(v3 - __bfloat162float(b3));
                *(__nv_bfloat162*)(Cb + (size_t)r0 * ldc + c0)       = pb0;
                *(__nv_bfloat162*)(Cb + (size_t)(r0 + 8) * ldc + c0) = pb1;
                *(__nv_bfloat162*)(Cs + (size_t)r0 * ldc + c0)       = ps0;
                *(__nv_bfloat162*)(Cs + (size_t)(r0 + 8) * ldc + c0) = ps1;
            } else {
                *(float2*)(Cf + (size_t)r0 * ldc + c0)       = make_float2(v0, v1);
                *(float2*)(Cf + (size_t)(r0 + 8) * ldc + c0) = make_float2(v2, v3);
            }
        }
    }
}

// ---------------- split fp32 -> bf16 big/small --------------------------------
__device__ __forceinline__ void split4(const float4 v, bf16* xb, bf16* xs, size_t i)
{
    bf16 b0 = __float2bfloat16(v.x), b1 = __float2bfloat16(v.y);
    bf16 b2 = __float2bfloat16(v.z), b3 = __float2bfloat16(v.w);
    __nv_bfloat162 pb0, pb1, ps0, ps1;
    pb0.x = b0; pb0.y = b1; pb1.x = b2; pb1.y = b3;
    ps0.x = __float2bfloat16(v.x - __bfloat162float(b0));
    ps0.y = __float2bfloat16(v.y - __bfloat162float(b1));
    ps1.x = __float2bfloat16(v.z - __bfloat162float(b2));
    ps1.y = __float2bfloat16(v.w - __bfloat162float(b3));
    *(__nv_bfloat162*)(xb + i)     = pb0;
    *(__nv_bfloat162*)(xb + i + 2) = pb1;
    *(__nv_bfloat162*)(xs + i)     = ps0;
    *(__nv_bfloat162*)(xs + i + 2) = ps1;
}

__global__ void split_kernel(const float* __restrict__ x,
                             bf16* __restrict__ xb, bf16* __restrict__ xs)
{
    size_t i = ((size_t)blockIdx.x * 256 + threadIdx.x) * 8;
    float4 v0 = *(const float4*)(x + i);
    float4 v1 = *(const float4*)(x + i + 4);
    split4(v0, xb, xs, i);
    split4(v1, xb, xs, i + 4);
}

__global__ void splitw_kernel(const float* __restrict__ W0, const float* __restrict__ W1,
                              const float* __restrict__ W2, const float* __restrict__ W3,
                              bf16* __restrict__ xb, bf16* __restrict__ xs)
{
    int w = blockIdx.y;
    const float* x = (w == 0) ? W0 : (w == 1) ? W1 : (w == 2) ? W2 : W3;
    size_t base = (size_t)w * HID * HID;
    size_t i = ((size_t)blockIdx.x * 256 + threadIdx.x) * 8;
    float4 v0 = *(const float4*)(x + i);
    float4 v1 = *(const float4*)(x + i + 4);
    split4(v0, xb + base, xs + base, i);
    split4(v1, xb + base, xs + base, i + 4);
}

// ---------------- MsPoE rotary -> split bf16 ----------------------------------
__global__ void rope_split_kernel(const float* __restrict__ q, const float* __restrict__ k,
                                  const int* __restrict__ pos_ids,
                                  bf16* __restrict__ qb, bf16* __restrict__ qs,
                                  bf16* __restrict__ kb, bf16* __restrict__ ks)
{
    int i = blockIdx.x * blockDim.x + threadIdx.x;
    int d = i & 63;
    int h = (i >> 6) & 31;
    int s = i >> 11;
    float ratio = 1.2f + (0.6f / 31.0f) * (float)h;
    float t = (float)pos_ids[s] / ratio;
    float inv_freq = exp2f(-(float)d * (13.287712379549449f / 64.0f));
    float f = t * inv_freq;
    float c, sn;
    sincosf(f, &sn, &c);
    size_t base = (size_t)s * HID + h * HD + d;

    float x1 = q[base], x2 = q[base + 64];
    float y0 = x1 * c - x2 * sn;
    float y1 = x2 * c + x1 * sn;
    bf16 t0 = __float2bfloat16(y0);
    bf16 t1 = __float2bfloat16(y1);
    qb[base] = t0;
    qs[base] = __float2bfloat16(y0 - __bfloat162float(t0));
    qb[base + 64] = t1;
    qs[base + 64] = __float2bfloat16(y1 - __bfloat162float(t1));

    x1 = k[base]; x2 = k[base + 64];
    y0 = x1 * c - x2 * sn;
    y1 = x2 * c + x1 * sn;
    t0 = __float2bfloat16(y0);
    t1 = __float2bfloat16(y1);
    kb[base] = t0;
    ks[base] = __float2bfloat16(y0 - __bfloat162float(t0));
    kb[base + 64] = t1;
    ks[base + 64] = __float2bfloat16(y1 - __bfloat162float(t1));
}

// ---------------- probs1: in-place softmax over k<=q ---------------------------
__global__ void probs1_kernel(float* __restrict__ scores)
{
    int q = blockIdx.x, h = blockIdx.y;
    float* row = scores + ((size_t)h * S + q) * S;
    __shared__ float red[256];
    int tid = threadIdx.x;

    float v[8];
    float m = -INFINITY;
#pragma unroll
    for (int j = 0; j < 8; j++) {
        int k = tid + j * 256;
        v[j] = (k <= q) ? row[k] : -INFINITY;
        m = fmaxf(m, v[j]);
    }
    red[tid] = m;
    __syncthreads();
    for (int st = 128; st; st >>= 1) {
        if (tid < st) red[tid] = fmaxf(red[tid], red[tid + st]);
        __syncthreads();
    }
    m = red[0];
    __syncthreads();

    float sum = 0.f;
#pragma unroll
    for (int j = 0; j < 8; j++) {
        v[j] = expf(v[j] - m);
        sum += v[j];
    }
    red[tid] = sum;
    __syncthreads();
    for (int st = 128; st; st >>= 1) {
        if (tid < st) red[tid] += red[tid + st];
        __syncthreads();
    }
    float inv = 1.0f / red[0];
#pragma unroll
    for (int j = 0; j < 8; j++) {
        int k = tid + j * 256;
        if (k <= q) row[k] = v[j] * inv;
    }
}

// ---------------- hh partial sums over q-chunks --------------------------------
__global__ void hh_part_kernel(const float* __restrict__ p1, float* __restrict__ part)
{
    int kb = blockIdx.x, qc = blockIdx.y, h = blockIdx.z;
    if (qc < kb) return;
    int k = kb * 256 + threadIdx.x;
    const float* base = p1 + (size_t)h * S * S;
    int q0 = qc * 256;
    float acc = 0.f;
    for (int q = q0; q < q0 + 256; q++) {
        if (q >= k) acc += base[(size_t)q * S + k];
    }
    part[((size_t)qc * NH + h) * S + k] = acc;
}

__global__ void hh_reduce_kernel(const float* __restrict__ part, float* __restrict__ hh)
{
    int h = blockIdx.y;
    int k = blockIdx.x * 256 + threadIdx.x;
    int kb = k >> 8;
    float acc = 0.f;
    for (int qc = kb; qc < 8; qc++)
        acc += part[((size_t)qc * NH + h) * S + k];
    hh[h * S + k] = acc;
}

// ---------------- per-head top-204 over hh[:SEL]; build key mask ---------------
__global__ void topk_mask_kernel(const float* __restrict__ hh, float* __restrict__ mask)
{
    int h = blockIdx.x;
    int tid = threadIdx.x;
    __shared__ float vals[SEL];
    __shared__ float rmax[256];
    __shared__ int   ridx[256];

    for (int i = tid; i < SEL; i += 256) vals[i] = hh[h * S + i];
    for (int k = tid; k < S; k += 256)  mask[h * S + k] = (k >= SEL) ? 0.f : NEGV;
    __syncthreads();

    for (int it = 0; it < HHSZ; it++) {
        float bm = -INFINITY;
        int bi = SEL;
        for (int i = tid; i < SEL; i += 256) {
            float v = vals[i];
            if (v > bm) { bm = v; bi = i; }
        }
        rmax[tid] = bm;
        ridx[tid] = bi;
        __syncthreads();
        for (int st = 128; st; st >>= 1) {
            if (tid < st) {
                if (rmax[tid + st] > rmax[tid] ||
                    (rmax[tid + st] == rmax[tid] && ridx[tid + st] < ridx[tid])) {
                    rmax[tid] = rmax[tid + st];
                    ridx[tid] = ridx[tid + st];
                }
            }
            __syncthreads();
        }
        if (tid == 0) {
            int kk = ridx[0];
            mask[h * S + kk] = 0.f;
            vals[kk] = -INFINITY;
        }
        __syncthreads();
    }
}

// ---------------- softmax2 = renormalize kept probs1; split bf16 out -----------
__global__ void softmax2_renorm_kernel(const float* __restrict__ p1,
                                       const float* __restrict__ mask,
                                       bf16* __restrict__ pb, bf16* __restrict__ ps)
{
    int q = blockIdx.x, h = blockIdx.y;
    size_t off = ((size_t)h * S + q) * S;
    const float* row = p1 + off;
    const float* mk = mask + h * S;
    __shared__ float red[256];
    int tid = threadIdx.x;
    int tend = ((q >> 7) + 1) << 7;

    float v[8];
    float sum = 0.f;
#pragma unroll
    for (int j = 0; j < 8; j++) {
        int k = tid + j * 256;
        bool kept = (k <= q) && ((mk[k] == 0.f) || (k == q));
        v[j] = kept ? row[k] : 0.f;
        sum += v[j];
    }
    red[tid] = sum;
    __syncthreads();
    for (int st = 128; st; st >>= 1) {
        if (tid < st) red[tid] += red[tid + st];
        __syncthreads();
    }
    float inv = 1.0f / red[0];
#pragma unroll
    for (int j = 0; j < 8; j++) {
        int k = tid + j * 256;
        if (k < tend) {
            float val = v[j] * inv;
            bf16 b = __float2bfloat16(val);
            pb[off + k] = b;
            ps[off + k] = __float2bfloat16(val - __bfloat162float(b));
        }
    }
}

// ---------------- launch --------------------------------------------------------
extern "C" void kernel_launch(void* const* d_in, const int* in_sizes, int n_in,
                              void* d_out, int out_size)
{
    const float* hs = (const float*)d_in[0];
    const float* W0 = (const float*)d_in[1];
    const float* W1 = (const float*)d_in[2];
    const float* W2 = (const float*)d_in[3];
    const float* W3 = (const float*)d_in[4];
    const int* pos = (const int*)d_in[5];
    float* out = (float*)d_out;

    float *q, *k, *scores, *hh, *hhp, *mask;
    bf16 *hsb, *hss, *wb, *ws, *qb, *qs, *kb, *ks, *vb, *vs, *pb, *ps, *ab, *as;
    cudaGetSymbolAddress((void**)&q, g_q);
    cudaGetSymbolAddress((void**)&k, g_k);
    cudaGetSymbolAddress((void**)&scores, g_scores);
    cudaGetSymbolAddress((void**)&hh, g_hh);
    cudaGetSymbolAddress((void**)&hhp, g_hhpart);
    cudaGetSymbolAddress((void**)&mask, g_mask);
    cudaGetSymbolAddress((void**)&hsb, g_hs_b);
    cudaGetSymbolAddress((void**)&hss, g_hs_s);
    cudaGetSymbolAddress((void**)&wb, g_w_b);
    cudaGetSymbolAddress((void**)&ws, g_w_s);
    cudaGetSymbolAddress((void**)&qb, g_qb);
    cudaGetSymbolAddress((void**)&qs, g_qs);
    cudaGetSymbolAddress((void**)&kb, g_kb);
    cudaGetSymbolAddress((void**)&ks, g_ks);
    cudaGetSymbolAddress((void**)&vb, g_vb);
    cudaGetSymbolAddress((void**)&vs, g_vs);
    cudaGetSymbolAddress((void**)&pb, g_pb);
    cudaGetSymbolAddress((void**)&ps, g_ps);
    cudaGetSymbolAddress((void**)&ab, g_ab);
    cudaGetSymbolAddress((void**)&as, g_as);

    const int SM_NT = (2 * (2 * ASZ + 2 * 128 * BNT_ST)) * 4;
    const int SM_NN = (2 * (2 * ASZ + 2 * 32 * BNN_ST)) * 4;
    cudaFuncSetAttribute(gemm_bf3<true, 0, false, true>,  cudaFuncAttributeMaxDynamicSharedMemorySize, SM_NT);
    cudaFuncSetAttribute(gemm_bf3<false, 2, true, false>, cudaFuncAttributeMaxDynamicSharedMemorySize, SM_NN);
    cudaFuncSetAttribute(gemm_big<0>, cudaFuncAttributeMaxDynamicSharedMemorySize, GB_SMEM);
    cudaFuncSetAttribute(gemm_big<2>, cudaFuncAttributeMaxDynamicSharedMemorySize, GB_SMEM);

    split_kernel<<<(S * HID) / 2048, 256>>>(hs, hsb, hss);
    splitw_kernel<<<dim3((HID * HID) / 2048, 4), 256>>>(W0, W1, W2, W3, wb, ws);

    dim3 gbig(HID / 128, S / 256);
    gemm_big<0><<<gbig, 512, GB_SMEM>>>(hsb, hss, HID,
        wb + 0 * (size_t)HID * HID, ws + 0 * (size_t)HID * HID, HID,
        q, (bf16*)0, (bf16*)0, HID, HID);
    gemm_big<0><<<gbig, 512, GB_SMEM>>>(hsb, hss, HID,
        wb + 1 * (size_t)HID * HID, ws + 1 * (size_t)HID * HID, HID,
        k, (bf16*)0, (bf16*)0, HID, HID);
    gemm_big<2><<<gbig, 512, GB_SMEM>>>(hsb, hss, HID,
        wb + 2 * (size_t)HID * HID, ws + 2 * (size_t)HID * HID, HID,
        (float*)0, vb, vs, HID, HID);

    rope_split_kernel<<<(S * NH * 64) / 256, 256>>>(q, k, pos, qb, qs, kb, ks);

    dim3 gs(136, 1, NH);
    gemm_bf3<true, 0, false, true><<<gs, 256, SM_NT>>>(
        qb, qs, HID, (size_t)HD, kb, ks, HID, (size_t)HD,
        scores, (bf16*)0, (bf16*)0, S, (size_t)S * S, HD, 0.08838834764831845f);

    probs1_kernel<<<dim3(S, NH), 256>>>(scores);
    hh_part_kernel<<<dim3(8, 8, NH), 256>>>(scores, hhp);
    hh_reduce_kernel<<<dim3(8, NH), 256>>>(hhp, hh);
    topk_mask_kernel<<<NH, 256>>>(hh, mask);
    softmax2_renorm_kernel<<<dim3(S, NH), 256>>>(scores, mask, pb, ps);

    dim3 gpv(HD / BN, 16, NH);
    gemm_bf3<false, 2, true, false><<<gpv, 256, SM_NN>>>(
        pb, ps, S, (size_t)S * S, vb, vs, HID, (size_t)HD,
        (float*)0, ab, as, HID, (size_t)HD, S, 1.f);

    gemm_big<0><<<gbig, 512, GB_SMEM>>>(ab, as, HID,
        wb + 3 * (size_t)HID * HID, ws + 3 * (size_t)HID * HID, HID,
        out, (bf16*)0, (bf16*)0, HID, HID);
}

// round 12
// speedup vs baseline: 1.0325x; 1.0325x over previous
#include <cuda_runtime.h>
#include <cuda_bf16.h>
#include <math.h>

#define S    2048
#define NH   32
#define HD   128
#define HID  4096
#define NEGV -1000000000.0f
#define HHSZ 204
#define RECENT 204
#define SEL  (S - RECENT)

typedef __nv_bfloat16 bf16;

// ---------------- scratch ----------------------------------------------------
__device__ float g_q[(size_t)S * HID];
__device__ float g_k[(size_t)S * HID];
__device__ float g_scores[(size_t)NH * S * S];
__device__ float g_hh[NH * S];
__device__ float g_hhpart[8 * NH * S];
__device__ float g_mask[NH * S];

__device__ bf16 g_hs_b[(size_t)S * HID],  g_hs_s[(size_t)S * HID];
__device__ bf16 g_w_b[4][(size_t)HID * HID], g_w_s[4][(size_t)HID * HID];
__device__ bf16 g_qb[(size_t)S * HID], g_qs[(size_t)S * HID];
__device__ bf16 g_kb[(size_t)S * HID], g_ks[(size_t)S * HID];
__device__ bf16 g_vb[(size_t)S * HID], g_vs[(size_t)S * HID];
__device__ bf16 g_pb[(size_t)NH * S * S], g_ps[(size_t)NH * S * S];
__device__ bf16 g_ab[(size_t)S * HID], g_as[(size_t)S * HID];

// ---------------- HMMA helpers (proven) --------------------------------------
__device__ __forceinline__ void mma_bf16(float c[4],
    unsigned a0, unsigned a1, unsigned a2, unsigned a3, unsigned b0, unsigned b1)
{
    asm volatile(
        "mma.sync.aligned.m16n8k16.row.col.f32.bf16.bf16.f32 "
        "{%0,%1,%2,%3}, {%4,%5,%6,%7}, {%8,%9}, {%0,%1,%2,%3};"
        : "+f"(c[0]), "+f"(c[1]), "+f"(c[2]), "+f"(c[3])
        : "r"(a0), "r"(a1), "r"(a2), "r"(a3), "r"(b0), "r"(b1));
}
__device__ __forceinline__ void ldsm_x4(unsigned r[4], unsigned addr)
{
    asm volatile("ldmatrix.sync.aligned.m8n8.x4.shared.b16 {%0,%1,%2,%3}, [%4];"
        : "=r"(r[0]), "=r"(r[1]), "=r"(r[2]), "=r"(r[3]) : "r"(addr));
}
__device__ __forceinline__ void ldsm_x4t(unsigned r[4], unsigned addr)
{
    asm volatile("ldmatrix.sync.aligned.m8n8.x4.trans.shared.b16 {%0,%1,%2,%3}, [%4];"
        : "=r"(r[0]), "=r"(r[1]), "=r"(r[2]), "=r"(r[3]) : "r"(addr));
}
__device__ __forceinline__ void cp16(unsigned dst, const void* src)
{
    asm volatile("cp.async.cg.shared.global [%0], [%1], 16;" :: "r"(dst), "l"(src));
}
__device__ __forceinline__ void cp_commit() { asm volatile("cp.async.commit_group;" ::: "memory"); }
__device__ __forceinline__ void cp_wait1() { asm volatile("cp.async.wait_group 1;" ::: "memory"); }
__device__ __forceinline__ void cp_wait0() { asm volatile("cp.async.wait_group 0;" ::: "memory"); }

// term-major MMA issue for one nj
#define MMA_NJ_BLOCK(accA, accB, accA2, accB2, abf, asf, bbf, bsf) do { \
    mma_bf16(accA,  (abf)[0][0], (abf)[0][1], (abf)[0][2], (abf)[0][3], (bsf)[0], (bsf)[1]); \
    mma_bf16(accB,  (abf)[0][0], (abf)[0][1], (abf)[0][2], (abf)[0][3], (bsf)[2], (bsf)[3]); \
    mma_bf16(accA2, (abf)[1][0], (abf)[1][1], (abf)[1][2], (abf)[1][3], (bsf)[0], (bsf)[1]); \
    mma_bf16(accB2, (abf)[1][0], (abf)[1][1], (abf)[1][2], (abf)[1][3], (bsf)[2], (bsf)[3]); \
    mma_bf16(accA,  (asf)[0][0], (asf)[0][1], (asf)[0][2], (asf)[0][3], (bbf)[0], (bbf)[1]); \
    mma_bf16(accB,  (asf)[0][0], (asf)[0][1], (asf)[0][2], (asf)[0][3], (bbf)[2], (bbf)[3]); \
    mma_bf16(accA2, (asf)[1][0], (asf)[1][1], (asf)[1][2], (asf)[1][3], (bbf)[0], (bbf)[1]); \
    mma_bf16(accB2, (asf)[1][0], (asf)[1][1], (asf)[1][2], (asf)[1][3], (bbf)[2], (bbf)[3]); \
    mma_bf16(accA,  (abf)[0][0], (abf)[0][1], (abf)[0][2], (abf)[0][3], (bbf)[0], (bbf)[1]); \
    mma_bf16(accB,  (abf)[0][0], (abf)[0][1], (abf)[0][2], (abf)[0][3], (bbf)[2], (bbf)[3]); \
    mma_bf16(accA2, (abf)[1][0], (abf)[1][1], (abf)[1][2], (abf)[1][3], (bbf)[0], (bbf)[1]); \
    mma_bf16(accB2, (abf)[1][0], (abf)[1][1], (abf)[1][2], (abf)[1][3], (bbf)[2], (bbf)[3]); \
} while (0)

// ================= big-M HMMA GEMM: 256x128 tile, 512 threads, NT ============
// 3-stage cp.async ring, ONE __syncthreads per k-tile.
#define GB_AST 20
#define GB_ASZ (256 * GB_AST)
#define GB_BSZ (128 * GB_AST)
#define GB_STG (2 * GB_ASZ + 2 * GB_BSZ)   // 15360 u32 per stage
#define GB_SMEM (3 * GB_STG * 4)           // 184320 B

template <int EPI>
__global__ __launch_bounds__(512, 1) void gemm_big(
    const bf16* __restrict__ Agb, const bf16* __restrict__ Ags, int lda,
    const bf16* __restrict__ Bgb, const bf16* __restrict__ Bgs, int ldb,
    float* __restrict__ Cf, bf16* __restrict__ Cb, bf16* __restrict__ Cs,
    int ldc, int K)
{
    const int bm = blockIdx.y * 256;
    const int bn = blockIdx.x * 128;
    const int tid  = threadIdx.x;
    const int wid  = tid >> 5;
    const int lane = tid & 31;
    const int g  = lane >> 2;
    const int tg = lane & 3;
    const int wm = (wid & 7) * 32;
    const int wn = (wid >> 3) * 64;

    extern __shared__ unsigned sm[];
    const unsigned smb = (unsigned)__cvta_generic_to_shared(sm);
    const int OFF_AB = 0, OFF_AS = GB_ASZ, OFF_BB = 2 * GB_ASZ, OFF_BS = 2 * GB_ASZ + GB_BSZ;

    const int T = K / 32;

    float acc[2][8][4];
#pragma unroll
    for (int i = 0; i < 2; i++)
#pragma unroll
        for (int j = 0; j < 8; j++)
#pragma unroll
            for (int t2 = 0; t2 < 4; t2++) acc[i][j][t2] = 0.f;

    const int a_row = (lane & 15);
    const int a_hi  = (lane >> 4) << 2;
    const int bnt_row = (lane & 7) + ((lane >> 4) & 1) * 8;
    const int bnt_hi  = ((lane >> 3) & 1) * 4;

    // loader indices
    const int arow0 = tid >> 2, aseg0 = tid & 3;

    // prefetch tiles 0 and 1
#pragma unroll
    for (int p = 0; p < 2; p++) {
        const int so = p * GB_STG;
        const int k0 = p * 32;
#pragma unroll
        for (int r = 0; r < 2; r++) {
            int s = tid + r * 512;
            int arow = s >> 2, aseg = s & 3;
            size_t aoff = (size_t)(bm + arow) * lda + k0 + aseg * 8;
            unsigned adst = smb + (so + OFF_AB + arow * GB_AST + aseg * 4) * 4;
            cp16(adst, Agb + aoff);
            cp16(adst + GB_ASZ * 4, Ags + aoff);
        }
        size_t boff = (size_t)(bn + arow0) * ldb + k0 + aseg0 * 8;
        unsigned bdst = smb + (so + OFF_BB + arow0 * GB_AST + aseg0 * 4) * 4;
        cp16(bdst, Bgb + boff);
        cp16(bdst + GB_BSZ * 4, Bgs + boff);
        cp_commit();
    }

    for (int t = 0; t < T; t++) {
        if (t + 1 < T) cp_wait1(); else cp_wait0();
        __syncthreads();

        // prefetch tile t+2 into buffer (t+2)%3 (last read at t-1; sync above covers it)
        if (t + 2 < T) {
            const int so = ((t + 2) % 3) * GB_STG;
            const int k0 = (t + 2) * 32;
#pragma unroll
            for (int r = 0; r < 2; r++) {
                int s = tid + r * 512;
                int arow = s >> 2, aseg = s & 3;
                size_t aoff = (size_t)(bm + arow) * lda + k0 + aseg * 8;
                unsigned adst = smb + (so + OFF_AB + arow * GB_AST + aseg * 4) * 4;
                cp16(adst, Agb + aoff);
                cp16(adst + GB_ASZ * 4, Ags + aoff);
            }
            size_t boff = (size_t)(bn + arow0) * ldb + k0 + aseg0 * 8;
            unsigned bdst = smb + (so + OFF_BB + arow0 * GB_AST + aseg0 * 4) * 4;
            cp16(bdst, Bgb + boff);
            cp16(bdst + GB_BSZ * 4, Bgs + boff);
            cp_commit();
        }

        const int so = (t % 3) * GB_STG;
#pragma unroll
        for (int kk = 0; kk < 2; kk++) {
            unsigned ab[2][4], as_[2][4];
#pragma unroll
            for (int mi = 0; mi < 2; mi++) {
                int idx = (wm + mi * 16 + a_row) * GB_AST + kk * 8 + a_hi;
                ldsm_x4(ab[mi],  smb + (so + OFF_AB + idx) * 4);
                ldsm_x4(as_[mi], smb + (so + OFF_AS + idx) * 4);
            }
#pragma unroll
            for (int nj = 0; nj < 4; nj++) {
                unsigned bb[4], bs[4];
                int idx = (wn + nj * 16 + bnt_row) * GB_AST + kk * 8 + bnt_hi;
                ldsm_x4(bb, smb + (so + OFF_BB + idx) * 4);
                ldsm_x4(bs, smb + (so + OFF_BS + idx) * 4);
                MMA_NJ_BLOCK(acc[0][2 * nj], acc[0][2 * nj + 1],
                             acc[1][2 * nj], acc[1][2 * nj + 1], ab, as_, bb, bs);
            }
        }
        // no trailing barrier: next iteration's sync gates buffer reuse
    }

#pragma unroll
    for (int mi = 0; mi < 2; mi++) {
#pragma unroll
        for (int ni = 0; ni < 8; ni++) {
            int r0 = bm + wm + mi * 16 + g;
            int c0 = bn + wn + ni * 8 + tg * 2;
            float v0 = acc[mi][ni][0];
            float v1 = acc[mi][ni][1];
            float v2 = acc[mi][ni][2];
            float v3 = acc[mi][ni][3];
            if (EPI == 2) {
                bf16 b0 = __float2bfloat16(v0), b1 = __float2bfloat16(v1);
                bf16 b2 = __float2bfloat16(v2), b3 = __float2bfloat16(v3);
                __nv_bfloat162 pb0, pb1, ps0, ps1;
                pb0.x = b0; pb0.y = b1; pb1.x = b2; pb1.y = b3;
                ps0.x = __float2bfloat16(v0 - __bfloat162float(b0));
                ps0.y = __float2bfloat16(v1 - __bfloat162float(b1));
                ps1.x = __float2bfloat16(v2 - __bfloat162float(b2));
                ps1.y = __float2bfloat16(v3 - __bfloat162float(b3));
                *(__nv_bfloat162*)(Cb + (size_t)r0 * ldc + c0)       = pb0;
                *(__nv_bfloat162*)(Cb + (size_t)(r0 + 8) * ldc + c0) = pb1;
                *(__nv_bfloat162*)(Cs + (size_t)r0 * ldc + c0)       = ps0;
                *(__nv_bfloat162*)(Cs + (size_t)(r0 + 8) * ldc + c0) = ps1;
            } else {
                *(float2*)(Cf + (size_t)r0 * ldc + c0)       = make_float2(v0, v1);
                *(float2*)(Cf + (size_t)(r0 + 8) * ldc + c0) = make_float2(v2, v3);
            }
        }
    }
}

// ================= HMMA bf16x3 GEMM 128x128 (QK lower-tri / PV) ==============
// 2-stage ring, ONE __syncthreads per k-tile.
#define BM 128
#define BN 128
#define BK 32
#define A_ST 20
#define ASZ  (128 * A_ST)
#define BNT_ST 20
#define BNN_ST 68

template <bool NT, int EPI, bool TRUNC, bool LOWER>
__global__ __launch_bounds__(256, 2) void gemm_bf3(
    const bf16* __restrict__ Agb, const bf16* __restrict__ Ags, int lda, size_t sA,
    const bf16* __restrict__ Bgb, const bf16* __restrict__ Bgs, int ldb, size_t sB,
    float* __restrict__ Cf, bf16* __restrict__ Cb, bf16* __restrict__ Cs,
    int ldc, size_t sC, int K, float alpha)
{
    const int bz = blockIdx.z;
    Agb += (size_t)bz * sA; Ags += (size_t)bz * sA;
    Bgb += (size_t)bz * sB; Bgs += (size_t)bz * sB;
    if (EPI == 2) { Cb += (size_t)bz * sC; Cs += (size_t)bz * sC; }
    else          { Cf += (size_t)bz * sC; }

    int bm, bn;
    if (LOWER) {
        int idx = blockIdx.x;
        int r = (int)((sqrtf(8.f * (float)idx + 1.f) - 1.f) * 0.5f);
        while ((r + 1) * (r + 2) / 2 <= idx) r++;
        while (r * (r + 1) / 2 > idx) r--;
        bm = r * BM;
        bn = (idx - r * (r + 1) / 2) * BN;
    } else if (TRUNC) {
        bm = (gridDim.y - 1 - blockIdx.y) * BM;
        bn = blockIdx.x * BN;
    } else {
        bm = blockIdx.y * BM;
        bn = blockIdx.x * BN;
    }

    const int tid  = threadIdx.x;
    const int wid  = tid >> 5;
    const int lane = tid & 31;
    const int g  = lane >> 2;
    const int tg = lane & 3;
    const int wm = (wid & 3) * 32;
    const int wn = (wid >> 2) * 64;

    extern __shared__ unsigned sm[];
    const unsigned smb = (unsigned)__cvta_generic_to_shared(sm);
    const int BSZ = NT ? (128 * BNT_ST) : (32 * BNN_ST);
    const int STG = 2 * ASZ + 2 * BSZ;
    const int OFF_AB = 0, OFF_AS = ASZ, OFF_BB = 2 * ASZ, OFF_BS = 2 * ASZ + BSZ;

    const int kend = TRUNC ? (bm + BM) : K;
    const int T = kend / BK;

    float acc[2][8][4];
#pragma unroll
    for (int i = 0; i < 2; i++)
#pragma unroll
        for (int j = 0; j < 8; j++)
#pragma unroll
            for (int t2 = 0; t2 < 4; t2++) acc[i][j][t2] = 0.f;

    const int a_row = (lane & 15);
    const int a_hi  = (lane >> 4) << 2;
    const int bnt_row = (lane & 7) + ((lane >> 4) & 1) * 8;
    const int bnt_hi  = ((lane >> 3) & 1) * 4;
    const int bnn_krow = (lane & 15);
    const int bnn_nhi  = ((lane >> 4) & 1) * 8;

    // prefetch tile 0
    {
        const int so = 0;
#pragma unroll
        for (int r = 0; r < 2; r++) {
            int s = tid + r * 256;
            int arow = s >> 2, aseg = s & 3;
            size_t aoff = (size_t)(bm + arow) * lda + aseg * 8;
            unsigned adst = smb + (so + OFF_AB + arow * A_ST + aseg * 4) * 4;
            cp16(adst, Agb + aoff);
            cp16(adst + ASZ * 4, Ags + aoff);
            if (NT) {
                size_t boff = (size_t)(bn + arow) * ldb + aseg * 8;
                unsigned bdst = smb + (so + OFF_BB + arow * BNT_ST + aseg * 4) * 4;
                cp16(bdst, Bgb + boff);
                cp16(bdst + BSZ * 4, Bgs + boff);
            } else {
                int krow = s >> 4, nseg = s & 15;
                size_t boff = (size_t)krow * ldb + bn + nseg * 8;
                unsigned bdst = smb + (so + OFF_BB + krow * BNN_ST + nseg * 4) * 4;
                cp16(bdst, Bgb + boff);
                cp16(bdst + BSZ * 4, Bgs + boff);
            }
        }
        cp_commit();
    }

    for (int t = 0; t < T; t++) {
        cp_wait0();
        __syncthreads();

        // prefetch t+1 into the other buffer (last read at t-1; sync covers it)
        if (t + 1 < T) {
            const int so = ((t + 1) & 1) * STG;
            const int k0 = (t + 1) * BK;
#pragma unroll
            for (int r = 0; r < 2; r++) {
                int s = tid + r * 256;
                int arow = s >> 2, aseg = s & 3;
                size_t aoff = (size_t)(bm + arow) * lda + k0 + aseg * 8;
                unsigned adst = smb + (so + OFF_AB + arow * A_ST + aseg * 4) * 4;
                cp16(adst, Agb + aoff);
                cp16(adst + ASZ * 4, Ags + aoff);
                if (NT) {
                    size_t boff = (size_t)(bn + arow) * ldb + k0 + aseg * 8;
                    unsigned bdst = smb + (so + OFF_BB + arow * BNT_ST + aseg * 4) * 4;
                    cp16(bdst, Bgb + boff);
                    cp16(bdst + BSZ * 4, Bgs + boff);
                } else {
                    int krow = s >> 4, nseg = s & 15;
                    size_t boff = (size_t)(k0 + krow) * ldb + bn + nseg * 8;
                    unsigned bdst = smb + (so + OFF_BB + krow * BNN_ST + nseg * 4) * 4;
                    cp16(bdst, Bgb + boff);
                    cp16(bdst + BSZ * 4, Bgs + boff);
                }
            }
            cp_commit();
        }

        const int so = (t & 1) * STG;
#pragma unroll
        for (int kk = 0; kk < 2; kk++) {
            unsigned ab[2][4], as_[2][4];
#pragma unroll
            for (int mi = 0; mi < 2; mi++) {
                int idx = (wm + mi * 16 + a_row) * A_ST + kk * 8 + a_hi;
                ldsm_x4(ab[mi],  smb + (so + OFF_AB + idx) * 4);
                ldsm_x4(as_[mi], smb + (so + OFF_AS + idx) * 4);
            }
#pragma unroll
            for (int nj = 0; nj < 4; nj++) {
                unsigned bb[4], bs[4];
                if (NT) {
                    int idx = (wn + nj * 16 + bnt_row) * BNT_ST + kk * 8 + bnt_hi;
                    ldsm_x4(bb, smb + (so + OFF_BB + idx) * 4);
                    ldsm_x4(bs, smb + (so + OFF_BS + idx) * 4);
                } else {
                    int idx = (kk * 16 + bnn_krow) * BNN_ST + ((wn + nj * 16 + bnn_nhi) >> 1);
                    ldsm_x4t(bb, smb + (so + OFF_BB + idx) * 4);
                    ldsm_x4t(bs, smb + (so + OFF_BS + idx) * 4);
                }
                MMA_NJ_BLOCK(acc[0][2 * nj], acc[0][2 * nj + 1],
                             acc[1][2 * nj], acc[1][2 * nj + 1], ab, as_, bb, bs);
            }
        }
    }

#pragma unroll
    for (int mi = 0; mi < 2; mi++) {
#pragma unroll
        for (int ni = 0; ni < 8; ni++) {
            int r0 = bm + wm + mi * 16 + g;
            int c0 = bn + wn + ni * 8 + tg * 2;
            float v0 = acc[mi][ni][0] * alpha;
            float v1 = acc[mi][ni][1] * alpha;
            float v2 = acc[mi][ni][2] * alpha;
            float v3 = acc[mi][ni][3] * alpha;
            if (EPI == 2) {
                bf16 b0 = __float2bfloat16(v0), b1 = __float2bfloat16(v1);
                bf16 b2 = __float2bfloat16(v2), b3 = __float2bfloat16(v3);
                __nv_bfloat162 pb0, pb1, ps0, ps1;
                pb0.x = b0; pb0.y = b1; pb1.x = b2; pb1.y = b3;
                ps0.x = __float2bfloat16(v0 - __bfloat162float(b0));
                ps0.y = __float2bfloat16(v1 - __bfloat162float(b1));
                ps1.x = __float2bfloat16(v2 - __bfloat162float(b2));
                ps1.y = __float2bfloat16(v3 - __bfloat162float(b3));
                *(__nv_bfloat162*)(Cb + (size_t)r0 * ldc + c0)       = pb0;
                *(__nv_bfloat162*)(Cb + (size_t)(r0 + 8) * ldc + c0) = pb1;
                *(__nv_bfloat162*)(Cs + (size_t)r0 * ldc + c0)       = ps0;
                *(__nv_bfloat162*)(Cs + (size_t)(r0 + 8) * ldc + c0) = ps1;
            } else {
                *(float2*)(Cf + (size_t)r0 * ldc + c0)       = make_float2(v0, v1);
                *(float2*)(Cf + (size_t)(r0 + 8) * ldc + c0) = make_float2(v2, v3);
            }
        }
    }
}

// ---------------- split fp32 -> bf16 big/small --------------------------------
__device__ __forceinline__ void split4(const float4 v, bf16* xb, bf16* xs, size_t i)
{
    bf16 b0 = __float2bfloat16(v.x), b1 = __float2bfloat16(v.y);
    bf16 b2 = __float2bfloat16(v.z), b3 = __float2bfloat16(v.w);
    __nv_bfloat162 pb0, pb1, ps0, ps1;
    pb0.x = b0; pb0.y = b1; pb1.x = b2; pb1.y = b3;
    ps0.x = __float2bfloat16(v.x - __bfloat162float(b0));
    ps0.y = __float2bfloat16(v.y - __bfloat162float(b1));
    ps1.x = __float2bfloat16(v.z - __bfloat162float(b2));
    ps1.y = __float2bfloat16(v.w - __bfloat162float(b3));
    *(__nv_bfloat162*)(xb + i)     = pb0;
    *(__nv_bfloat162*)(xb + i + 2) = pb1;
    *(__nv_bfloat162*)(xs + i)     = ps0;
    *(__nv_bfloat162*)(xs + i + 2) = ps1;
}

__global__ void split_kernel(const float* __restrict__ x,
                             bf16* __restrict__ xb, bf16* __restrict__ xs)
{
    size_t i = ((size_t)blockIdx.x * 256 + threadIdx.x) * 8;
    float4 v0 = *(const float4*)(x + i);
    float4 v1 = *(const float4*)(x + i + 4);
    split4(v0, xb, xs, i);
    split4(v1, xb, xs, i + 4);
}

__global__ void splitw_kernel(const float* __restrict__ W0, const float* __restrict__ W1,
                              const float* __restrict__ W2, const float* __restrict__ W3,
                              bf16* __restrict__ xb, bf16* __restrict__ xs)
{
    int w = blockIdx.y;
    const float* x = (w == 0) ? W0 : (w == 1) ? W1 : (w == 2) ? W2 : W3;
    size_t base = (size_t)w * HID * HID;
    size_t i = ((size_t)blockIdx.x * 256 + threadIdx.x) * 8;
    float4 v0 = *(const float4*)(x + i);
    float4 v1 = *(const float4*)(x + i + 4);
    split4(v0, xb + base, xs + base, i);
    split4(v1, xb + base, xs + base, i + 4);
}

// ---------------- MsPoE rotary -> split bf16 ----------------------------------
__global__ void rope_split_kernel(const float* __restrict__ q, const float* __restrict__ k,
                                  const int* __restrict__ pos_ids,
                                  bf16* __restrict__ qb, bf16* __restrict__ qs,
                                  bf16* __restrict__ kb, bf16* __restrict__ ks)
{
    int i = blockIdx.x * blockDim.x + threadIdx.x;
    int d = i & 63;
    int h = (i >> 6) & 31;
    int s = i >> 11;
    float ratio = 1.2f + (0.6f / 31.0f) * (float)h;
    float t = (float)pos_ids[s] / ratio;
    float inv_freq = exp2f(-(float)d * (13.287712379549449f / 64.0f));
    float f = t * inv_freq;
    float c, sn;
    sincosf(f, &sn, &c);
    size_t base = (size_t)s * HID + h * HD + d;

    float x1 = q[base], x2 = q[base + 64];
    float y0 = x1 * c - x2 * sn;
    float y1 = x2 * c + x1 * sn;
    bf16 t0 = __float2bfloat16(y0);
    bf16 t1 = __float2bfloat16(y1);
    qb[base] = t0;
    qs[base] = __float2bfloat16(y0 - __bfloat162float(t0));
    qb[base + 64] = t1;
    qs[base + 64] = __float2bfloat16(y1 - __bfloat162float(t1));

    x1 = k[base]; x2 = k[base + 64];
    y0 = x1 * c - x2 * sn;
    y1 = x2 * c + x1 * sn;
    t0 = __float2bfloat16(y0);
    t1 = __float2bfloat16(y1);
    kb[base] = t0;
    ks[base] = __float2bfloat16(y0 - __bfloat162float(t0));
    kb[base + 64] = t1;
    ks[base + 64] = __float2bfloat16(y1 - __bfloat162float(t1));
}

// ---------------- probs1: in-place softmax over k<=q ---------------------------
__global__ void probs1_kernel(float* __restrict__ scores)
{
    int q = blockIdx.x, h = blockIdx.y;
    float* row = scores + ((size_t)h * S + q) * S;
    __shared__ float red[256];
    int tid = threadIdx.x;

    float v[8];
    float m = -INFINITY;
#pragma unroll
    for (int j = 0; j < 8; j++) {
        int k = tid + j * 256;
        v[j] = (k <= q) ? row[k] : -INFINITY;
        m = fmaxf(m, v[j]);
    }
    red[tid] = m;
    __syncthreads();
    for (int st = 128; st; st >>= 1) {
        if (tid < st) red[tid] = fmaxf(red[tid], red[tid + st]);
        __syncthreads();
    }
    m = red[0];
    __syncthreads();

    float sum = 0.f;
#pragma unroll
    for (int j = 0; j < 8; j++) {
        v[j] = expf(v[j] - m);
        sum += v[j];
    }
    red[tid] = sum;
    __syncthreads();
    for (int st = 128; st; st >>= 1) {
        if (tid < st) red[tid] += red[tid + st];
        __syncthreads();
    }
    float inv = 1.0f / red[0];
#pragma unroll
    for (int j = 0; j < 8; j++) {
        int k = tid + j * 256;
        if (k <= q) row[k] = v[j] * inv;
    }
}

// ---------------- hh partial sums over q-chunks --------------------------------
__global__ void hh_part_kernel(const float* __restrict__ p1, float* __restrict__ part)
{
    int kb = blockIdx.x, qc = blockIdx.y, h = blockIdx.z;
    if (qc < kb) return;
    int k = kb * 256 + threadIdx.x;
    const float* base = p1 + (size_t)h * S * S;
    int q0 = qc * 256;
    float acc = 0.f;
    for (int q = q0; q < q0 + 256; q++) {
        if (q >= k) acc += base[(size_t)q * S + k];
    }
    part[((size_t)qc * NH + h) * S + k] = acc;
}

__global__ void hh_reduce_kernel(const float* __restrict__ part, float* __restrict__ hh)
{
    int h = blockIdx.y;
    int k = blockIdx.x * 256 + threadIdx.x;
    int kb = k >> 8;
    float acc = 0.f;
    for (int qc = kb; qc < 8; qc++)
        acc += part[((size_t)qc * NH + h) * S + k];
    hh[h * S + k] = acc;
}

// ---------------- per-head top-204 over hh[:SEL]; build key mask ---------------
__global__ void topk_mask_kernel(const float* __restrict__ hh, float* __restrict__ mask)
{
    int h = blockIdx.x;
    int tid = threadIdx.x;
    __shared__ float vals[SEL];
    __shared__ float rmax[256];
    __shared__ int   ridx[256];

    for (int i = tid; i < SEL; i += 256) vals[i] = hh[h * S + i];
    for (int k = tid; k < S; k += 256)  mask[h * S + k] = (k >= SEL) ? 0.f : NEGV;
    __syncthreads();

    for (int it = 0; it < HHSZ; it++) {
        float bm = -INFINITY;
        int bi = SEL;
        for (int i = tid; i < SEL; i += 256) {
            float v = vals[i];
            if (v > bm) { bm = v; bi = i; }
        }
        rmax[tid] = bm;
        ridx[tid] = bi;
        __syncthreads();
        for (int st = 128; st; st >>= 1) {
            if (tid < st) {
                if (rmax[tid + st] > rmax[tid] ||
                    (rmax[tid + st] == rmax[tid] && ridx[tid + st] < ridx[tid])) {
                    rmax[tid] = rmax[tid + st];
                    ridx[tid] = ridx[tid + st];
                }
            }
            __syncthreads();
        }
        if (tid == 0) {
            int kk = ridx[0];
            mask[h * S + kk] = 0.f;
            vals[kk] = -INFINITY;
        }
        __syncthreads();
    }
}

// ---------------- softmax2 = renormalize kept probs1; split bf16 out -----------
__global__ void softmax2_renorm_kernel(const float* __restrict__ p1,
                                       const float* __restrict__ mask,
                                       bf16* __restrict__ pb, bf16* __restrict__ ps)
{
    int q = blockIdx.x, h = blockIdx.y;
    size_t off = ((size_t)h * S + q) * S;
    const float* row = p1 + off;
    const float* mk = mask + h * S;
    __shared__ float red[256];
    int tid = threadIdx.x;
    int tend = ((q >> 7) + 1) << 7;

    float v[8];
    float sum = 0.f;
#pragma unroll
    for (int j = 0; j < 8; j++) {
        int k = tid + j * 256;
        bool kept = (k <= q) && ((mk[k] == 0.f) || (k == q));
        v[j] = kept ? row[k] : 0.f;
        sum += v[j];
    }
    red[tid] = sum;
    __syncthreads();
    for (int st = 128; st; st >>= 1) {
        if (tid < st) red[tid] += red[tid + st];
        __syncthreads();
    }
    float inv = 1.0f / red[0];
#pragma unroll
    for (int j = 0; j < 8; j++) {
        int k = tid + j * 256;
        if (k < tend) {
            float val = v[j] * inv;
            bf16 b = __float2bfloat16(val);
            pb[off + k] = b;
            ps[off + k] = __float2bfloat16(val - __bfloat162float(b));
        }
    }
}

// ---------------- launch --------------------------------------------------------
extern "C" void kernel_launch(void* const* d_in, const int* in_sizes, int n_in,
                              void* d_out, int out_size)
{
    const float* hs = (const float*)d_in[0];
    const float* W0 = (const float*)d_in[1];
    const float* W1 = (const float*)d_in[2];
    const float* W2 = (const float*)d_in[3];
    const float* W3 = (const float*)d_in[4];
    const int* pos = (const int*)d_in[5];
    float* out = (float*)d_out;

    float *q, *k, *scores, *hh, *hhp, *mask;
    bf16 *hsb, *hss, *wb, *ws, *qb, *qs, *kb, *ks, *vb, *vs, *pb, *ps, *ab, *as;
    cudaGetSymbolAddress((void**)&q, g_q);
    cudaGetSymbolAddress((void**)&k, g_k);
    cudaGetSymbolAddress((void**)&scores, g_scores);
    cudaGetSymbolAddress((void**)&hh, g_hh);
    cudaGetSymbolAddress((void**)&hhp, g_hhpart);
    cudaGetSymbolAddress((void**)&mask, g_mask);
    cudaGetSymbolAddress((void**)&hsb, g_hs_b);
    cudaGetSymbolAddress((void**)&hss, g_hs_s);
    cudaGetSymbolAddress((void**)&wb, g_w_b);
    cudaGetSymbolAddress((void**)&ws, g_w_s);
    cudaGetSymbolAddress((void**)&qb, g_qb);
    cudaGetSymbolAddress((void**)&qs, g_qs);
    cudaGetSymbolAddress((void**)&kb, g_kb);
    cudaGetSymbolAddress((void**)&ks, g_ks);
    cudaGetSymbolAddress((void**)&vb, g_vb);
    cudaGetSymbolAddress((void**)&vs, g_vs);
    cudaGetSymbolAddress((void**)&pb, g_pb);
    cudaGetSymbolAddress((void**)&ps, g_ps);
    cudaGetSymbolAddress((void**)&ab, g_ab);
    cudaGetSymbolAddress((void**)&as, g_as);

    const int SM_NT = (2 * (2 * ASZ + 2 * 128 * BNT_ST)) * 4;
    const int SM_NN = (2 * (2 * ASZ + 2 * 32 * BNN_ST)) * 4;
    cudaFuncSetAttribute(gemm_bf3<true, 0, false, true>,  cudaFuncAttributeMaxDynamicSharedMemorySize, SM_NT);
    cudaFuncSetAttribute(gemm_bf3<false, 2, true, false>, cudaFuncAttributeMaxDynamicSharedMemorySize, SM_NN);
    cudaFuncSetAttribute(gemm_big<0>, cudaFuncAttributeMaxDynamicSharedMemorySize, GB_SMEM);
    cudaFuncSetAttribute(gemm_big<2>, cudaFuncAttributeMaxDynamicSharedMemorySize, GB_SMEM);

    split_kernel<<<(S * HID) / 2048, 256>>>(hs, hsb, hss);
    splitw_kernel<<<dim3((HID * HID) / 2048, 4), 256>>>(W0, W1, W2, W3, wb, ws);

    dim3 gbig(HID / 128, S / 256);
    gemm_big<0><<<gbig, 512, GB_SMEM>>>(hsb, hss, HID,
        wb + 0 * (size_t)HID * HID, ws + 0 * (size_t)HID * HID, HID,
        q, (bf16*)0, (bf16*)0, HID, HID);
    gemm_big<0><<<gbig, 512, GB_SMEM>>>(hsb, hss, HID,
        wb + 1 * (size_t)HID * HID, ws + 1 * (size_t)HID * HID, HID,
        k, (bf16*)0, (bf16*)0, HID, HID);
    gemm_big<2><<<gbig, 512, GB_SMEM>>>(hsb, hss, HID,
        wb + 2 * (size_t)HID * HID, ws + 2 * (size_t)HID * HID, HID,
        (float*)0, vb, vs, HID, HID);

    rope_split_kernel<<<(S * NH * 64) / 256, 256>>>(q, k, pos, qb, qs, kb, ks);

    dim3 gs(136, 1, NH);
    gemm_bf3<true, 0, false, true><<<gs, 256, SM_NT>>>(
        qb, qs, HID, (size_t)HD, kb, ks, HID, (size_t)HD,
        scores, (bf16*)0, (bf16*)0, S, (size_t)S * S, HD, 0.08838834764831845f);

    probs1_kernel<<<dim3(S, NH), 256>>>(scores);
    hh_part_kernel<<<dim3(8, 8, NH), 256>>>(scores, hhp);
    hh_reduce_kernel<<<dim3(8, NH), 256>>>(hhp, hh);
    topk_mask_kernel<<<NH, 256>>>(hh, mask);
    softmax2_renorm_kernel<<<dim3(S, NH), 256>>>(scores, mask, pb, ps);

    dim3 gpv(HD / BN, 16, NH);
    gemm_bf3<false, 2, true, false><<<gpv, 256, SM_NN>>>(
        pb, ps, S, (size_t)S * S, vb, vs, HID, (size_t)HD,
        (float*)0, ab, as, HID, (size_t)HD, S, 1.f);

    gemm_big<0><<<gbig, 512, GB_SMEM>>>(ab, as, HID,
        wb + 3 * (size_t)HID * HID, ws + 3 * (size_t)HID * HID, HID,
        out, (bf16*)0, (bf16*)0, HID, HID);
}

// round 13
// speedup vs baseline: 1.0420x; 1.0092x over previous
#include <cuda_runtime.h>
#include <cuda_bf16.h>
#include <math.h>

#define S    2048
#define NH   32
#define HD   128
#define HID  4096
#define NEGV -1000000000.0f
#define HHSZ 204
#define RECENT 204
#define SEL  (S - RECENT)

typedef __nv_bfloat16 bf16;

// ---------------- scratch ----------------------------------------------------
__device__ float g_q[(size_t)S * HID];
__device__ float g_k[(size_t)S * HID];
__device__ float g_scores[(size_t)NH * S * S];
__device__ float g_hh[NH * S];
__device__ float g_hhpart[8 * NH * S];
__device__ float g_mask[NH * S];

__device__ bf16 g_hs_b[(size_t)S * HID],  g_hs_s[(size_t)S * HID];
__device__ bf16 g_w_b[4][(size_t)HID * HID], g_w_s[4][(size_t)HID * HID];
__device__ bf16 g_qb[(size_t)S * HID], g_qs[(size_t)S * HID];
__device__ bf16 g_kb[(size_t)S * HID], g_ks[(size_t)S * HID];
__device__ bf16 g_vb[(size_t)S * HID], g_vs[(size_t)S * HID];
__device__ bf16 g_pb[(size_t)NH * S * S], g_ps[(size_t)NH * S * S];
__device__ bf16 g_ab[(size_t)S * HID], g_as[(size_t)S * HID];

// ---------------- HMMA helpers (proven) --------------------------------------
__device__ __forceinline__ void mma_bf16(float c[4],
    unsigned a0, unsigned a1, unsigned a2, unsigned a3, unsigned b0, unsigned b1)
{
    asm volatile(
        "mma.sync.aligned.m16n8k16.row.col.f32.bf16.bf16.f32 "
        "{%0,%1,%2,%3}, {%4,%5,%6,%7}, {%8,%9}, {%0,%1,%2,%3};"
        : "+f"(c[0]), "+f"(c[1]), "+f"(c[2]), "+f"(c[3])
        : "r"(a0), "r"(a1), "r"(a2), "r"(a3), "r"(b0), "r"(b1));
}
__device__ __forceinline__ void ldsm_x4(unsigned r[4], unsigned addr)
{
    asm volatile("ldmatrix.sync.aligned.m8n8.x4.shared.b16 {%0,%1,%2,%3}, [%4];"
        : "=r"(r[0]), "=r"(r[1]), "=r"(r[2]), "=r"(r[3]) : "r"(addr));
}
__device__ __forceinline__ void ldsm_x4t(unsigned r[4], unsigned addr)
{
    asm volatile("ldmatrix.sync.aligned.m8n8.x4.trans.shared.b16 {%0,%1,%2,%3}, [%4];"
        : "=r"(r[0]), "=r"(r[1]), "=r"(r[2]), "=r"(r[3]) : "r"(addr));
}
__device__ __forceinline__ void cp16(unsigned dst, const void* src)
{
    asm volatile("cp.async.cg.shared.global [%0], [%1], 16;" :: "r"(dst), "l"(src));
}
__device__ __forceinline__ void cp_commit() { asm volatile("cp.async.commit_group;" ::: "memory"); }
__device__ __forceinline__ void cp_wait0() { asm volatile("cp.async.wait_group 0;" ::: "memory"); }

// term-major MMA issue for one nj
#define MMA_NJ_BLOCK(accA, accB, accA2, accB2, abf, asf, bbf, bsf) do { \
    mma_bf16(accA,  (abf)[0][0], (abf)[0][1], (abf)[0][2], (abf)[0][3], (bsf)[0], (bsf)[1]); \
    mma_bf16(accB,  (abf)[0][0], (abf)[0][1], (abf)[0][2], (abf)[0][3], (bsf)[2], (bsf)[3]); \
    mma_bf16(accA2, (abf)[1][0], (abf)[1][1], (abf)[1][2], (abf)[1][3], (bsf)[0], (bsf)[1]); \
    mma_bf16(accB2, (abf)[1][0], (abf)[1][1], (abf)[1][2], (abf)[1][3], (bsf)[2], (bsf)[3]); \
    mma_bf16(accA,  (asf)[0][0], (asf)[0][1], (asf)[0][2], (asf)[0][3], (bbf)[0], (bbf)[1]); \
    mma_bf16(accB,  (asf)[0][0], (asf)[0][1], (asf)[0][2], (asf)[0][3], (bbf)[2], (bbf)[3]); \
    mma_bf16(accA2, (asf)[1][0], (asf)[1][1], (asf)[1][2], (asf)[1][3], (bbf)[0], (bbf)[1]); \
    mma_bf16(accB2, (asf)[1][0], (asf)[1][1], (asf)[1][2], (asf)[1][3], (bbf)[2], (bbf)[3]); \
    mma_bf16(accA,  (abf)[0][0], (abf)[0][1], (abf)[0][2], (abf)[0][3], (bbf)[0], (bbf)[1]); \
    mma_bf16(accB,  (abf)[0][0], (abf)[0][1], (abf)[0][2], (abf)[0][3], (bbf)[2], (bbf)[3]); \
    mma_bf16(accA2, (abf)[1][0], (abf)[1][1], (abf)[1][2], (abf)[1][3], (bbf)[0], (bbf)[1]); \
    mma_bf16(accB2, (abf)[1][0], (abf)[1][1], (abf)[1][2], (abf)[1][3], (bbf)[2], (bbf)[3]); \
} while (0)

// ================= HMMA bf16x3 GEMM 128x128, single-barrier 2-stage ==========
#define BM 128
#define BN 128
#define BK 32
#define A_ST 20
#define ASZ  (128 * A_ST)
#define BNT_ST 20
#define BNN_ST 68

template <bool NT, int EPI, bool TRUNC, bool LOWER>
__global__ __launch_bounds__(256, 2) void gemm_bf3(
    const bf16* __restrict__ Agb, const bf16* __restrict__ Ags, int lda, size_t sA,
    const bf16* __restrict__ Bgb, const bf16* __restrict__ Bgs, int ldb, size_t sB,
    float* __restrict__ Cf, bf16* __restrict__ Cb, bf16* __restrict__ Cs,
    int ldc, size_t sC, int K, float alpha)
{
    const int bz = blockIdx.z;
    Agb += (size_t)bz * sA; Ags += (size_t)bz * sA;
    Bgb += (size_t)bz * sB; Bgs += (size_t)bz * sB;
    if (EPI == 2) { Cb += (size_t)bz * sC; Cs += (size_t)bz * sC; }
    else          { Cf += (size_t)bz * sC; }

    int bm, bn;
    if (LOWER) {
        int idx = blockIdx.x;
        int r = (int)((sqrtf(8.f * (float)idx + 1.f) - 1.f) * 0.5f);
        while ((r + 1) * (r + 2) / 2 <= idx) r++;
        while (r * (r + 1) / 2 > idx) r--;
        bm = r * BM;
        bn = (idx - r * (r + 1) / 2) * BN;
    } else if (TRUNC) {
        bm = (gridDim.y - 1 - blockIdx.y) * BM;
        bn = blockIdx.x * BN;
    } else {
        bm = blockIdx.y * BM;
        bn = blockIdx.x * BN;
    }

    const int tid  = threadIdx.x;
    const int wid  = tid >> 5;
    const int lane = tid & 31;
    const int g  = lane >> 2;
    const int tg = lane & 3;
    const int wm = (wid & 3) * 32;
    const int wn = (wid >> 2) * 64;

    extern __shared__ unsigned sm[];
    const unsigned smb = (unsigned)__cvta_generic_to_shared(sm);
    const int BSZ = NT ? (128 * BNT_ST) : (32 * BNN_ST);
    const int STG = 2 * ASZ + 2 * BSZ;
    const int OFF_AB = 0, OFF_AS = ASZ, OFF_BB = 2 * ASZ, OFF_BS = 2 * ASZ + BSZ;

    const int kend = TRUNC ? (bm + BM) : K;
    const int T = kend / BK;

    float acc[2][8][4];
#pragma unroll
    for (int i = 0; i < 2; i++)
#pragma unroll
        for (int j = 0; j < 8; j++)
#pragma unroll
            for (int t2 = 0; t2 < 4; t2++) acc[i][j][t2] = 0.f;

    const int a_row = (lane & 15);
    const int a_hi  = (lane >> 4) << 2;
    const int bnt_row = (lane & 7) + ((lane >> 4) & 1) * 8;
    const int bnt_hi  = ((lane >> 3) & 1) * 4;
    const int bnn_krow = (lane & 15);
    const int bnn_nhi  = ((lane >> 4) & 1) * 8;

    // prefetch tile 0
    {
        const int so = 0;
#pragma unroll
        for (int r = 0; r < 2; r++) {
            int s = tid + r * 256;
            int arow = s >> 2, aseg = s & 3;
            size_t aoff = (size_t)(bm + arow) * lda + aseg * 8;
            unsigned adst = smb + (so + OFF_AB + arow * A_ST + aseg * 4) * 4;
            cp16(adst, Agb + aoff);
            cp16(adst + ASZ * 4, Ags + aoff);
            if (NT) {
                size_t boff = (size_t)(bn + arow) * ldb + aseg * 8;
                unsigned bdst = smb + (so + OFF_BB + arow * BNT_ST + aseg * 4) * 4;
                cp16(bdst, Bgb + boff);
                cp16(bdst + BSZ * 4, Bgs + boff);
            } else {
                int krow = s >> 4, nseg = s & 15;
                size_t boff = (size_t)krow * ldb + bn + nseg * 8;
                unsigned bdst = smb + (so + OFF_BB + krow * BNN_ST + nseg * 4) * 4;
                cp16(bdst, Bgb + boff);
                cp16(bdst + BSZ * 4, Bgs + boff);
            }
        }
        cp_commit();
    }

    for (int t = 0; t < T; t++) {
        cp_wait0();
        __syncthreads();

        // prefetch t+1 into the other buffer (single barrier gates reuse)
        if (t + 1 < T) {
            const int so = ((t + 1) & 1) * STG;
            const int k0 = (t + 1) * BK;
#pragma unroll
            for (int r = 0; r < 2; r++) {
                int s = tid + r * 256;
                int arow = s >> 2, aseg = s & 3;
                size_t aoff = (size_t)(bm + arow) * lda + k0 + aseg * 8;
                unsigned adst = smb + (so + OFF_AB + arow * A_ST + aseg * 4) * 4;
                cp16(adst, Agb + aoff);
                cp16(adst + ASZ * 4, Ags + aoff);
                if (NT) {
                    size_t boff = (size_t)(bn + arow) * ldb + k0 + aseg * 8;
                    unsigned bdst = smb + (so + OFF_BB + arow * BNT_ST + aseg * 4) * 4;
                    cp16(bdst, Bgb + boff);
                    cp16(bdst + BSZ * 4, Bgs + boff);
                } else {
                    int krow = s >> 4, nseg = s & 15;
                    size_t boff = (size_t)(k0 + krow) * ldb + bn + nseg * 8;
                    unsigned bdst = smb + (so + OFF_BB + krow * BNN_ST + nseg * 4) * 4;
                    cp16(bdst, Bgb + boff);
                    cp16(bdst + BSZ * 4, Bgs + boff);
                }
            }
            cp_commit();
        }

        const int so = (t & 1) * STG;
#pragma unroll
        for (int kk = 0; kk < 2; kk++) {
            unsigned ab[2][4], as_[2][4];
#pragma unroll
            for (int mi = 0; mi < 2; mi++) {
                int idx = (wm + mi * 16 + a_row) * A_ST + kk * 8 + a_hi;
                ldsm_x4(ab[mi],  smb + (so + OFF_AB + idx) * 4);
                ldsm_x4(as_[mi], smb + (so + OFF_AS + idx) * 4);
            }
#pragma unroll
            for (int nj = 0; nj < 4; nj++) {
                unsigned bb[4], bs[4];
                if (NT) {
                    int idx = (wn + nj * 16 + bnt_row) * BNT_ST + kk * 8 + bnt_hi;
                    ldsm_x4(bb, smb + (so + OFF_BB + idx) * 4);
                    ldsm_x4(bs, smb + (so + OFF_BS + idx) * 4);
                } else {
                    int idx = (kk * 16 + bnn_krow) * BNN_ST + ((wn + nj * 16 + bnn_nhi) >> 1);
                    ldsm_x4t(bb, smb + (so + OFF_BB + idx) * 4);
                    ldsm_x4t(bs, smb + (so + OFF_BS + idx) * 4);
                }
                MMA_NJ_BLOCK(acc[0][2 * nj], acc[0][2 * nj + 1],
                             acc[1][2 * nj], acc[1][2 * nj + 1], ab, as_, bb, bs);
            }
        }
    }

#pragma unroll
    for (int mi = 0; mi < 2; mi++) {
#pragma unroll
        for (int ni = 0; ni < 8; ni++) {
            int r0 = bm + wm + mi * 16 + g;
            int c0 = bn + wn + ni * 8 + tg * 2;
            float v0 = acc[mi][ni][0] * alpha;
            float v1 = acc[mi][ni][1] * alpha;
            float v2 = acc[mi][ni][2] * alpha;
            float v3 = acc[mi][ni][3] * alpha;
            if (EPI == 2) {
                bf16 b0 = __float2bfloat16(v0), b1 = __float2bfloat16(v1);
                bf16 b2 = __float2bfloat16(v2), b3 = __float2bfloat16(v3);
                __nv_bfloat162 pb0, pb1, ps0, ps1;
                pb0.x = b0; pb0.y = b1; pb1.x = b2; pb1.y = b3;
                ps0.x = __float2bfloat16(v0 - __bfloat162float(b0));
                ps0.y = __float2bfloat16(v1 - __bfloat162float(b1));
                ps1.x = __float2bfloat16(v2 - __bfloat162float(b2));
                ps1.y = __float2bfloat16(v3 - __bfloat162float(b3));
                *(__nv_bfloat162*)(Cb + (size_t)r0 * ldc + c0)       = pb0;
                *(__nv_bfloat162*)(Cb + (size_t)(r0 + 8) * ldc + c0) = pb1;
                *(__nv_bfloat162*)(Cs + (size_t)r0 * ldc + c0)       = ps0;
                *(__nv_bfloat162*)(Cs + (size_t)(r0 + 8) * ldc + c0) = ps1;
            } else {
                *(float2*)(Cf + (size_t)r0 * ldc + c0)       = make_float2(v0, v1);
                *(float2*)(Cf + (size_t)(r0 + 8) * ldc + c0) = make_float2(v2, v3);
            }
        }
    }
}

// ---------------- split fp32 -> bf16 big/small --------------------------------
__device__ __forceinline__ void split4(const float4 v, bf16* xb, bf16* xs, size_t i)
{
    bf16 b0 = __float2bfloat16(v.x), b1 = __float2bfloat16(v.y);
    bf16 b2 = __float2bfloat16(v.z), b3 = __float2bfloat16(v.w);
    __nv_bfloat162 pb0, pb1, ps0, ps1;
    pb0.x = b0; pb0.y = b1; pb1.x = b2; pb1.y = b3;
    ps0.x = __float2bfloat16(v.x - __bfloat162float(b0));
    ps0.y = __float2bfloat16(v.y - __bfloat162float(b1));
    ps1.x = __float2bfloat16(v.z - __bfloat162float(b2));
    ps1.y = __float2bfloat16(v.w - __bfloat162float(b3));
    *(__nv_bfloat162*)(xb + i)     = pb0;
    *(__nv_bfloat162*)(xb + i + 2) = pb1;
    *(__nv_bfloat162*)(xs + i)     = ps0;
    *(__nv_bfloat162*)(xs + i + 2) = ps1;
}

__global__ void split_kernel(const float* __restrict__ x,
                             bf16* __restrict__ xb, bf16* __restrict__ xs)
{
    size_t i = ((size_t)blockIdx.x * 256 + threadIdx.x) * 8;
    float4 v0 = *(const float4*)(x + i);
    float4 v1 = *(const float4*)(x + i + 4);
    split4(v0, xb, xs, i);
    split4(v1, xb, xs, i + 4);
}

__global__ void splitw_kernel(const float* __restrict__ W0, const float* __restrict__ W1,
                              const float* __restrict__ W2, const float* __restrict__ W3,
                              bf16* __restrict__ xb, bf16* __restrict__ xs)
{
    int w = blockIdx.y;
    const float* x = (w == 0) ? W0 : (w == 1) ? W1 : (w == 2) ? W2 : W3;
    size_t base = (size_t)w * HID * HID;
    size_t i = ((size_t)blockIdx.x * 256 + threadIdx.x) * 8;
    float4 v0 = *(const float4*)(x + i);
    float4 v1 = *(const float4*)(x + i + 4);
    split4(v0, xb + base, xs + base, i);
    split4(v1, xb + base, xs + base, i + 4);
}

// ---------------- MsPoE rotary -> split bf16 ----------------------------------
__global__ void rope_split_kernel(const float* __restrict__ q, const float* __restrict__ k,
                                  const int* __restrict__ pos_ids,
                                  bf16* __restrict__ qb, bf16* __restrict__ qs,
                                  bf16* __restrict__ kb, bf16* __restrict__ ks)
{
    int i = blockIdx.x * blockDim.x + threadIdx.x;
    int d = i & 63;
    int h = (i >> 6) & 31;
    int s = i >> 11;
    float ratio = 1.2f + (0.6f / 31.0f) * (float)h;
    float t = (float)pos_ids[s] / ratio;
    float inv_freq = exp2f(-(float)d * (13.287712379549449f / 64.0f));
    float f = t * inv_freq;
    float c, sn;
    sincosf(f, &sn, &c);
    size_t base = (size_t)s * HID + h * HD + d;

    float x1 = q[base], x2 = q[base + 64];
    float y0 = x1 * c - x2 * sn;
    float y1 = x2 * c + x1 * sn;
    bf16 t0 = __float2bfloat16(y0);
    bf16 t1 = __float2bfloat16(y1);
    qb[base] = t0;
    qs[base] = __float2bfloat16(y0 - __bfloat162float(t0));
    qb[base + 64] = t1;
    qs[base + 64] = __float2bfloat16(y1 - __bfloat162float(t1));

    x1 = k[base]; x2 = k[base + 64];
    y0 = x1 * c - x2 * sn;
    y1 = x2 * c + x1 * sn;
    t0 = __float2bfloat16(y0);
    t1 = __float2bfloat16(y1);
    kb[base] = t0;
    ks[base] = __float2bfloat16(y0 - __bfloat162float(t0));
    kb[base + 64] = t1;
    ks[base + 64] = __float2bfloat16(y1 - __bfloat162float(t1));
}

// ---------------- probs1: in-place softmax over k<=q ---------------------------
__global__ void probs1_kernel(float* __restrict__ scores)
{
    int q = blockIdx.x, h = blockIdx.y;
    float* row = scores + ((size_t)h * S + q) * S;
    __shared__ float red[256];
    int tid = threadIdx.x;

    float v[8];
    float m = -INFINITY;
#pragma unroll
    for (int j = 0; j < 8; j++) {
        int k = tid + j * 256;
        v[j] = (k <= q) ? row[k] : -INFINITY;
        m = fmaxf(m, v[j]);
    }
    red[tid] = m;
    __syncthreads();
    for (int st = 128; st; st >>= 1) {
        if (tid < st) red[tid] = fmaxf(red[tid], red[tid + st]);
        __syncthreads();
    }
    m = red[0];
    __syncthreads();

    float sum = 0.f;
#pragma unroll
    for (int j = 0; j < 8; j++) {
        v[j] = expf(v[j] - m);
        sum += v[j];
    }
    red[tid] = sum;
    __syncthreads();
    for (int st = 128; st; st >>= 1) {
        if (tid < st) red[tid] += red[tid + st];
        __syncthreads();
    }
    float inv = 1.0f / red[0];
#pragma unroll
    for (int j = 0; j < 8; j++) {
        int k = tid + j * 256;
        if (k <= q) row[k] = v[j] * inv;
    }
}

// ---------------- hh partial sums over q-chunks --------------------------------
__global__ void hh_part_kernel(const float* __restrict__ p1, float* __restrict__ part)
{
    int kb = blockIdx.x, qc = blockIdx.y, h = blockIdx.z;
    if (qc < kb) return;
    int k = kb * 256 + threadIdx.x;
    const float* base = p1 + (size_t)h * S * S;
    int q0 = qc * 256;
    float acc = 0.f;
    for (int q = q0; q < q0 + 256; q++) {
        if (q >= k) acc += base[(size_t)q * S + k];
    }
    part[((size_t)qc * NH + h) * S + k] = acc;
}

__global__ void hh_reduce_kernel(const float* __restrict__ part, float* __restrict__ hh)
{
    int h = blockIdx.y;
    int k = blockIdx.x * 256 + threadIdx.x;
    int kb = k >> 8;
    float acc = 0.f;
    for (int qc = kb; qc < 8; qc++)
        acc += part[((size_t)qc * NH + h) * S + k];
    hh[h * S + k] = acc;
}

// ---------------- per-head top-204 over hh[:SEL]; build key mask ---------------
__global__ void topk_mask_kernel(const float* __restrict__ hh, float* __restrict__ mask)
{
    int h = blockIdx.x;
    int tid = threadIdx.x;
    __shared__ float vals[SEL];
    __shared__ float rmax[256];
    __shared__ int   ridx[256];

    for (int i = tid; i < SEL; i += 256) vals[i] = hh[h * S + i];
    for (int k = tid; k < S; k += 256)  mask[h * S + k] = (k >= SEL) ? 0.f : NEGV;
    __syncthreads();

    for (int it = 0; it < HHSZ; it++) {
        float bm = -INFINITY;
        int bi = SEL;
        for (int i = tid; i < SEL; i += 256) {
            float v = vals[i];
            if (v > bm) { bm = v; bi = i; }
        }
        rmax[tid] = bm;
        ridx[tid] = bi;
        __syncthreads();
        for (int st = 128; st; st >>= 1) {
            if (tid < st) {
                if (rmax[tid + st] > rmax[tid] ||
                    (rmax[tid + st] == rmax[tid] && ridx[tid + st] < ridx[tid])) {
                    rmax[tid] = rmax[tid + st];
                    ridx[tid] = ridx[tid + st];
                }
            }
            __syncthreads();
        }
        if (tid == 0) {
            int kk = ridx[0];
            mask[h * S + kk] = 0.f;
            vals[kk] = -INFINITY;
        }
        __syncthreads();
    }
}

// ---------------- softmax2 = renormalize kept probs1; split bf16 out -----------
__global__ void softmax2_renorm_kernel(const float* __restrict__ p1,
                                       const float* __restrict__ mask,
                                       bf16* __restrict__ pb, bf16* __restrict__ ps)
{
    int q = blockIdx.x, h = blockIdx.y;
    size_t off = ((size_t)h * S + q) * S;
    const float* row = p1 + off;
    const float* mk = mask + h * S;
    __shared__ float red[256];
    int tid = threadIdx.x;
    int tend = ((q >> 7) + 1) << 7;

    float v[8];
    float sum = 0.f;
#pragma unroll
    for (int j = 0; j < 8; j++) {
        int k = tid + j * 256;
        bool kept = (k <= q) && ((mk[k] == 0.f) || (k == q));
        v[j] = kept ? row[k] : 0.f;
        sum += v[j];
    }
    red[tid] = sum;
    __syncthreads();
    for (int st = 128; st; st >>= 1) {
        if (tid < st) red[tid] += red[tid + st];
        __syncthreads();
    }
    float inv = 1.0f / red[0];
#pragma unroll
    for (int j = 0; j < 8; j++) {
        int k = tid + j * 256;
        if (k < tend) {
            float val = v[j] * inv;
            bf16 b = __float2bfloat16(val);
            pb[off + k] = b;
            ps[off + k] = __float2bfloat16(val - __bfloat162float(b));
        }
    }
}

// ---------------- launch --------------------------------------------------------
extern "C" void kernel_launch(void* const* d_in, const int* in_sizes, int n_in,
                              void* d_out, int out_size)
{
    const float* hs = (const float*)d_in[0];
    const float* W0 = (const float*)d_in[1];
    const float* W1 = (const float*)d_in[2];
    const float* W2 = (const float*)d_in[3];
    const float* W3 = (const float*)d_in[4];
    const int* pos = (const int*)d_in[5];
    float* out = (float*)d_out;

    float *q, *k, *scores, *hh, *hhp, *mask;
    bf16 *hsb, *hss, *wb, *ws, *qb, *qs, *kb, *ks, *vb, *vs, *pb, *ps, *ab, *as;
    cudaGetSymbolAddress((void**)&q, g_q);
    cudaGetSymbolAddress((void**)&k, g_k);
    cudaGetSymbolAddress((void**)&scores, g_scores);
    cudaGetSymbolAddress((void**)&hh, g_hh);
    cudaGetSymbolAddress((void**)&hhp, g_hhpart);
    cudaGetSymbolAddress((void**)&mask, g_mask);
    cudaGetSymbolAddress((void**)&hsb, g_hs_b);
    cudaGetSymbolAddress((void**)&hss, g_hs_s);
    cudaGetSymbolAddress((void**)&wb, g_w_b);
    cudaGetSymbolAddress((void**)&ws, g_w_s);
    cudaGetSymbolAddress((void**)&qb, g_qb);
    cudaGetSymbolAddress((void**)&qs, g_qs);
    cudaGetSymbolAddress((void**)&kb, g_kb);
    cudaGetSymbolAddress((void**)&ks, g_ks);
    cudaGetSymbolAddress((void**)&vb, g_vb);
    cudaGetSymbolAddress((void**)&vs, g_vs);
    cudaGetSymbolAddress((void**)&pb, g_pb);
    cudaGetSymbolAddress((void**)&ps, g_ps);
    cudaGetSymbolAddress((void**)&ab, g_ab);
    cudaGetSymbolAddress((void**)&as, g_as);

    const int SM_NT = (2 * (2 * ASZ + 2 * 128 * BNT_ST)) * 4;
    const int SM_NN = (2 * (2 * ASZ + 2 * 32 * BNN_ST)) * 4;
    cudaFuncSetAttribute(gemm_bf3<true, 0, false, false>, cudaFuncAttributeMaxDynamicSharedMemorySize, SM_NT);
    cudaFuncSetAttribute(gemm_bf3<true, 2, false, false>, cudaFuncAttributeMaxDynamicSharedMemorySize, SM_NT);
    cudaFuncSetAttribute(gemm_bf3<true, 0, false, true>,  cudaFuncAttributeMaxDynamicSharedMemorySize, SM_NT);
    cudaFuncSetAttribute(gemm_bf3<false, 2, true, false>, cudaFuncAttributeMaxDynamicSharedMemorySize, SM_NN);

    split_kernel<<<(S * HID) / 2048, 256>>>(hs, hsb, hss);
    splitw_kernel<<<dim3((HID * HID) / 2048, 4), 256>>>(W0, W1, W2, W3, wb, ws);

    // projections (128x128, 2 CTA/SM, single-barrier pipeline)
    dim3 gp(HID / BN, S / BM, 1);
    gemm_bf3<true, 0, false, false><<<gp, 256, SM_NT>>>(
        hsb, hss, HID, 0, wb + 0 * (size_t)HID * HID, ws + 0 * (size_t)HID * HID, HID, 0,
        q, (bf16*)0, (bf16*)0, HID, 0, HID, 1.f);
    gemm_bf3<true, 0, false, false><<<gp, 256, SM_NT>>>(
        hsb, hss, HID, 0, wb + 1 * (size_t)HID * HID, ws + 1 * (size_t)HID * HID, HID, 0,
        k, (bf16*)0, (bf16*)0, HID, 0, HID, 1.f);
    gemm_bf3<true, 2, false, false><<<gp, 256, SM_NT>>>(
        hsb, hss, HID, 0, wb + 2 * (size_t)HID * HID, ws + 2 * (size_t)HID * HID, HID, 0,
        (float*)0, vb, vs, HID, 0, HID, 1.f);

    rope_split_kernel<<<(S * NH * 64) / 256, 256>>>(q, k, pos, qb, qs, kb, ks);

    dim3 gs(136, 1, NH);
    gemm_bf3<true, 0, false, true><<<gs, 256, SM_NT>>>(
        qb, qs, HID, (size_t)HD, kb, ks, HID, (size_t)HD,
        scores, (bf16*)0, (bf16*)0, S, (size_t)S * S, HD, 0.08838834764831845f);

    probs1_kernel<<<dim3(S, NH), 256>>>(scores);
    hh_part_kernel<<<dim3(8, 8, NH), 256>>>(scores, hhp);
    hh_reduce_kernel<<<dim3(8, NH), 256>>>(hhp, hh);
    topk_mask_kernel<<<NH, 256>>>(hh, mask);
    softmax2_renorm_kernel<<<dim3(S, NH), 256>>>(scores, mask, pb, ps);

    dim3 gpv(HD / BN, 16, NH);
    gemm_bf3<false, 2, true, false><<<gpv, 256, SM_NN>>>(
        pb, ps, S, (size_t)S * S, vb, vs, HID, (size_t)HD,
        (float*)0, ab, as, HID, (size_t)HD, S, 1.f);

    gemm_bf3<true, 0, false, false><<<gp, 256, SM_NT>>>(
        ab, as, HID, 0, wb + 3 * (size_t)HID * HID, ws + 3 * (size_t)HID * HID, HID, 0,
        out, (bf16*)0, (bf16*)0, HID, 0, HID, 1.f);
}

// round 14
// speedup vs baseline: 1.1014x; 1.0570x over previous
#include <cuda_runtime.h>
#include <cuda_bf16.h>
#include <math.h>

#define S    2048
#define NH   32
#define HD   128
#define HID  4096
#define NEGV -1000000000.0f
#define HHSZ 204
#define RECENT 204
#define SEL  (S - RECENT)

typedef __nv_bfloat16 bf16;

// ---------------- scratch ----------------------------------------------------
__device__ float g_q[(size_t)S * HID];
__device__ float g_k[(size_t)S * HID];
__device__ float g_scores[(size_t)NH * S * S];
__device__ float g_hh[NH * S];
__device__ float g_hhpart[8 * NH * S];
__device__ float g_mask[NH * S];

__device__ bf16 g_hs_b[(size_t)S * HID],  g_hs_s[(size_t)S * HID];
__device__ bf16 g_w_b[4][(size_t)HID * HID], g_w_s[4][(size_t)HID * HID];
__device__ bf16 g_qb[(size_t)S * HID], g_qs[(size_t)S * HID];
__device__ bf16 g_kb[(size_t)S * HID], g_ks[(size_t)S * HID];
__device__ bf16 g_vb[(size_t)S * HID], g_vs[(size_t)S * HID];
__device__ bf16 g_pb[(size_t)NH * S * S], g_ps[(size_t)NH * S * S];
__device__ bf16 g_ab[(size_t)S * HID], g_as[(size_t)S * HID];

// ---------------- HMMA helpers (proven) --------------------------------------
__device__ __forceinline__ void mma_bf16(float c[4],
    unsigned a0, unsigned a1, unsigned a2, unsigned a3, unsigned b0, unsigned b1)
{
    asm volatile(
        "mma.sync.aligned.m16n8k16.row.col.f32.bf16.bf16.f32 "
        "{%0,%1,%2,%3}, {%4,%5,%6,%7}, {%8,%9}, {%0,%1,%2,%3};"
        : "+f"(c[0]), "+f"(c[1]), "+f"(c[2]), "+f"(c[3])
        : "r"(a0), "r"(a1), "r"(a2), "r"(a3), "r"(b0), "r"(b1));
}
__device__ __forceinline__ void ldsm_x4(unsigned r[4], unsigned addr)
{
    asm volatile("ldmatrix.sync.aligned.m8n8.x4.shared.b16 {%0,%1,%2,%3}, [%4];"
        : "=r"(r[0]), "=r"(r[1]), "=r"(r[2]), "=r"(r[3]) : "r"(addr));
}
__device__ __forceinline__ void ldsm_x4t(unsigned r[4], unsigned addr)
{
    asm volatile("ldmatrix.sync.aligned.m8n8.x4.trans.shared.b16 {%0,%1,%2,%3}, [%4];"
        : "=r"(r[0]), "=r"(r[1]), "=r"(r[2]), "=r"(r[3]) : "r"(addr));
}
__device__ __forceinline__ void cp16(unsigned dst, const void* src)
{
    asm volatile("cp.async.cg.shared.global [%0], [%1], 16;" :: "r"(dst), "l"(src));
}
__device__ __forceinline__ void cp_commit() { asm volatile("cp.async.commit_group;" ::: "memory"); }
__device__ __forceinline__ void cp_wait0() { asm volatile("cp.async.wait_group 0;" ::: "memory"); }

// term-major MMA issue for one nj
#define MMA_NJ_BLOCK(accA, accB, accA2, accB2, abf, asf, bbf, bsf) do { \
    mma_bf16(accA,  (abf)[0][0], (abf)[0][1], (abf)[0][2], (abf)[0][3], (bsf)[0], (bsf)[1]); \
    mma_bf16(accB,  (abf)[0][0], (abf)[0][1], (abf)[0][2], (abf)[0][3], (bsf)[2], (bsf)[3]); \
    mma_bf16(accA2, (abf)[1][0], (abf)[1][1], (abf)[1][2], (abf)[1][3], (bsf)[0], (bsf)[1]); \
    mma_bf16(accB2, (abf)[1][0], (abf)[1][1], (abf)[1][2], (abf)[1][3], (bsf)[2], (bsf)[3]); \
    mma_bf16(accA,  (asf)[0][0], (asf)[0][1], (asf)[0][2], (asf)[0][3], (bbf)[0], (bbf)[1]); \
    mma_bf16(accB,  (asf)[0][0], (asf)[0][1], (asf)[0][2], (asf)[0][3], (bbf)[2], (bbf)[3]); \
    mma_bf16(accA2, (asf)[1][0], (asf)[1][1], (asf)[1][2], (asf)[1][3], (bbf)[0], (bbf)[1]); \
    mma_bf16(accB2, (asf)[1][0], (asf)[1][1], (asf)[1][2], (asf)[1][3], (bbf)[2], (bbf)[3]); \
    mma_bf16(accA,  (abf)[0][0], (abf)[0][1], (abf)[0][2], (abf)[0][3], (bbf)[0], (bbf)[1]); \
    mma_bf16(accB,  (abf)[0][0], (abf)[0][1], (abf)[0][2], (abf)[0][3], (bbf)[2], (bbf)[3]); \
    mma_bf16(accA2, (abf)[1][0], (abf)[1][1], (abf)[1][2], (abf)[1][3], (bbf)[0], (bbf)[1]); \
    mma_bf16(accB2, (abf)[1][0], (abf)[1][1], (abf)[1][2], (abf)[1][3], (bbf)[2], (bbf)[3]); \
} while (0)

// ================= HMMA bf16x3 GEMM 128x128, single-barrier 2-stage ==========
// EPI: 0 fp32 store, 2 split-bf16 store, 3 QKV-fused (bz selects dest/format)
#define BM 128
#define BN 128
#define BK 32
#define A_ST 20
#define ASZ  (128 * A_ST)
#define BNT_ST 20
#define BNN_ST 68

template <bool NT, int EPI, bool TRUNC, bool LOWER>
__global__ __launch_bounds__(256, 2) void gemm_bf3(
    const bf16* __restrict__ Agb, const bf16* __restrict__ Ags, int lda, size_t sA,
    const bf16* __restrict__ Bgb, const bf16* __restrict__ Bgs, int ldb, size_t sB,
    float* __restrict__ Cf, float* __restrict__ Cf2,
    bf16* __restrict__ Cb, bf16* __restrict__ Cs,
    int ldc, size_t sC, int K, float alpha)
{
    const int bz = blockIdx.z;
    Agb += (size_t)bz * sA; Ags += (size_t)bz * sA;
    Bgb += (size_t)bz * sB; Bgs += (size_t)bz * sB;
    if (EPI == 2) { Cb += (size_t)bz * sC; Cs += (size_t)bz * sC; }
    else if (EPI == 0) { Cf += (size_t)bz * sC; }

    int bm, bn;
    if (LOWER) {
        int idx = blockIdx.x;
        int r = (int)((sqrtf(8.f * (float)idx + 1.f) - 1.f) * 0.5f);
        while ((r + 1) * (r + 2) / 2 <= idx) r++;
        while (r * (r + 1) / 2 > idx) r--;
        bm = r * BM;
        bn = (idx - r * (r + 1) / 2) * BN;
    } else if (TRUNC) {
        bm = (gridDim.y - 1 - blockIdx.y) * BM;
        bn = blockIdx.x * BN;
    } else {
        bm = blockIdx.y * BM;
        bn = blockIdx.x * BN;
    }

    const int tid  = threadIdx.x;
    const int wid  = tid >> 5;
    const int lane = tid & 31;
    const int g  = lane >> 2;
    const int tg = lane & 3;
    const int wm = (wid & 3) * 32;
    const int wn = (wid >> 2) * 64;

    extern __shared__ unsigned sm[];
    const unsigned smb = (unsigned)__cvta_generic_to_shared(sm);
    const int BSZ = NT ? (128 * BNT_ST) : (32 * BNN_ST);
    const int STG = 2 * ASZ + 2 * BSZ;
    const int OFF_AB = 0, OFF_AS = ASZ, OFF_BB = 2 * ASZ, OFF_BS = 2 * ASZ + BSZ;

    const int kend = TRUNC ? (bm + BM) : K;
    const int T = kend / BK;

    float acc[2][8][4];
#pragma unroll
    for (int i = 0; i < 2; i++)
#pragma unroll
        for (int j = 0; j < 8; j++)
#pragma unroll
            for (int t2 = 0; t2 < 4; t2++) acc[i][j][t2] = 0.f;

    const int a_row = (lane & 15);
    const int a_hi  = (lane >> 4) << 2;
    const int bnt_row = (lane & 7) + ((lane >> 4) & 1) * 8;
    const int bnt_hi  = ((lane >> 3) & 1) * 4;
    const int bnn_krow = (lane & 15);
    const int bnn_nhi  = ((lane >> 4) & 1) * 8;

    // prefetch tile 0
    {
        const int so = 0;
#pragma unroll
        for (int r = 0; r < 2; r++) {
            int s = tid + r * 256;
            int arow = s >> 2, aseg = s & 3;
            size_t aoff = (size_t)(bm + arow) * lda + aseg * 8;
            unsigned adst = smb + (so + OFF_AB + arow * A_ST + aseg * 4) * 4;
            cp16(adst, Agb + aoff);
            cp16(adst + ASZ * 4, Ags + aoff);
            if (NT) {
                size_t boff = (size_t)(bn + arow) * ldb + aseg * 8;
                unsigned bdst = smb + (so + OFF_BB + arow * BNT_ST + aseg * 4) * 4;
                cp16(bdst, Bgb + boff);
                cp16(bdst + BSZ * 4, Bgs + boff);
            } else {
                int krow = s >> 4, nseg = s & 15;
                size_t boff = (size_t)krow * ldb + bn + nseg * 8;
                unsigned bdst = smb + (so + OFF_BB + krow * BNN_ST + nseg * 4) * 4;
                cp16(bdst, Bgb + boff);
                cp16(bdst + BSZ * 4, Bgs + boff);
            }
        }
        cp_commit();
    }

    for (int t = 0; t < T; t++) {
        cp_wait0();
        __syncthreads();

        if (t + 1 < T) {
            const int so = ((t + 1) & 1) * STG;
            const int k0 = (t + 1) * BK;
#pragma unroll
            for (int r = 0; r < 2; r++) {
                int s = tid + r * 256;
                int arow = s >> 2, aseg = s & 3;
                size_t aoff = (size_t)(bm + arow) * lda + k0 + aseg * 8;
                unsigned adst = smb + (so + OFF_AB + arow * A_ST + aseg * 4) * 4;
                cp16(adst, Agb + aoff);
                cp16(adst + ASZ * 4, Ags + aoff);
                if (NT) {
                    size_t boff = (size_t)(bn + arow) * ldb + k0 + aseg * 8;
                    unsigned bdst = smb + (so + OFF_BB + arow * BNT_ST + aseg * 4) * 4;
                    cp16(bdst, Bgb + boff);
                    cp16(bdst + BSZ * 4, Bgs + boff);
                } else {
                    int krow = s >> 4, nseg = s & 15;
                    size_t boff = (size_t)(k0 + krow) * ldb + bn + nseg * 8;
                    unsigned bdst = smb + (so + OFF_BB + krow * BNN_ST + nseg * 4) * 4;
                    cp16(bdst, Bgb + boff);
                    cp16(bdst + BSZ * 4, Bgs + boff);
                }
            }
            cp_commit();
        }

        const int so = (t & 1) * STG;
#pragma unroll
        for (int kk = 0; kk < 2; kk++) {
            unsigned ab[2][4], as_[2][4];
#pragma unroll
            for (int mi = 0; mi < 2; mi++) {
                int idx = (wm + mi * 16 + a_row) * A_ST + kk * 8 + a_hi;
                ldsm_x4(ab[mi],  smb + (so + OFF_AB + idx) * 4);
                ldsm_x4(as_[mi], smb + (so + OFF_AS + idx) * 4);
            }
#pragma unroll
            for (int nj = 0; nj < 4; nj++) {
                unsigned bb[4], bs[4];
                if (NT) {
                    int idx = (wn + nj * 16 + bnt_row) * BNT_ST + kk * 8 + bnt_hi;
                    ldsm_x4(bb, smb + (so + OFF_BB + idx) * 4);
                    ldsm_x4(bs, smb + (so + OFF_BS + idx) * 4);
                } else {
                    int idx = (kk * 16 + bnn_krow) * BNN_ST + ((wn + nj * 16 + bnn_nhi) >> 1);
                    ldsm_x4t(bb, smb + (so + OFF_BB + idx) * 4);
                    ldsm_x4t(bs, smb + (so + OFF_BS + idx) * 4);
                }
                MMA_NJ_BLOCK(acc[0][2 * nj], acc[0][2 * nj + 1],
                             acc[1][2 * nj], acc[1][2 * nj + 1], ab, as_, bb, bs);
            }
        }
    }

    const bool split_out = (EPI == 2) || (EPI == 3 && bz == 2);
    float* fout = (EPI == 3) ? ((bz == 1) ? Cf2 : Cf) : Cf;

#pragma unroll
    for (int mi = 0; mi < 2; mi++) {
#pragma unroll
        for (int ni = 0; ni < 8; ni++) {
            int r0 = bm + wm + mi * 16 + g;
            int c0 = bn + wn + ni * 8 + tg * 2;
            float v0 = acc[mi][ni][0] * alpha;
            float v1 = acc[mi][ni][1] * alpha;
            float v2 = acc[mi][ni][2] * alpha;
            float v3 = acc[mi][ni][3] * alpha;
            if (split_out) {
                bf16 b0 = __float2bfloat16(v0), b1 = __float2bfloat16(v1);
                bf16 b2 = __float2bfloat16(v2), b3 = __float2bfloat16(v3);
                __nv_bfloat162 pb0, pb1, ps0, ps1;
                pb0.x = b0; pb0.y = b1; pb1.x = b2; pb1.y = b3;
                ps0.x = __float2bfloat16(v0 - __bfloat162float(b0));
                ps0.y = __float2bfloat16(v1 - __bfloat162float(b1));
                ps1.x = __float2bfloat16(v2 - __bfloat162float(b2));
                ps1.y = __float2bfloat16(v3 - __bfloat162float(b3));
                *(__nv_bfloat162*)(Cb + (size_t)r0 * ldc + c0)       = pb0;
                *(__nv_bfloat162*)(Cb + (size_t)(r0 + 8) * ldc + c0) = pb1;
                *(__nv_bfloat162*)(Cs + (size_t)r0 * ldc + c0)       = ps0;
                *(__nv_bfloat162*)(Cs + (size_t)(r0 + 8) * ldc + c0) = ps1;
            } else {
                *(float2*)(fout + (size_t)r0 * ldc + c0)       = make_float2(v0, v1);
                *(float2*)(fout + (size_t)(r0 + 8) * ldc + c0) = make_float2(v2, v3);
            }
        }
    }
}

// ---------------- split fp32 -> bf16 big/small --------------------------------
__device__ __forceinline__ void split4(const float4 v, bf16* xb, bf16* xs, size_t i)
{
    bf16 b0 = __float2bfloat16(v.x), b1 = __float2bfloat16(v.y);
    bf16 b2 = __float2bfloat16(v.z), b3 = __float2bfloat16(v.w);
    __nv_bfloat162 pb0, pb1, ps0, ps1;
    pb0.x = b0; pb0.y = b1; pb1.x = b2; pb1.y = b3;
    ps0.x = __float2bfloat16(v.x - __bfloat162float(b0));
    ps0.y = __float2bfloat16(v.y - __bfloat162float(b1));
    ps1.x = __float2bfloat16(v.z - __bfloat162float(b2));
    ps1.y = __float2bfloat16(v.w - __bfloat162float(b3));
    *(__nv_bfloat162*)(xb + i)     = pb0;
    *(__nv_bfloat162*)(xb + i + 2) = pb1;
    *(__nv_bfloat162*)(xs + i)     = ps0;
    *(__nv_bfloat162*)(xs + i + 2) = ps1;
}

__global__ void split_kernel(const float* __restrict__ x,
                             bf16* __restrict__ xb, bf16* __restrict__ xs)
{
    size_t i = ((size_t)blockIdx.x * 256 + threadIdx.x) * 8;
    float4 v0 = *(const float4*)(x + i);
    float4 v1 = *(const float4*)(x + i + 4);
    split4(v0, xb, xs, i);
    split4(v1, xb, xs, i + 4);
}

__global__ void splitw_kernel(const float* __restrict__ W0, const float* __restrict__ W1,
                              const float* __restrict__ W2, const float* __restrict__ W3,
                              bf16* __restrict__ xb, bf16* __restrict__ xs)
{
    int w = blockIdx.y;
    const float* x = (w == 0) ? W0 : (w == 1) ? W1 : (w == 2) ? W2 : W3;
    size_t base = (size_t)w * HID * HID;
    size_t i = ((size_t)blockIdx.x * 256 + threadIdx.x) * 8;
    float4 v0 = *(const float4*)(x + i);
    float4 v1 = *(const float4*)(x + i + 4);
    split4(v0, xb + base, xs + base, i);
    split4(v1, xb + base, xs + base, i + 4);
}

// ---------------- MsPoE rotary -> split bf16 ----------------------------------
__global__ void rope_split_kernel(const float* __restrict__ q, const float* __restrict__ k,
                                  const int* __restrict__ pos_ids,
                                  bf16* __restrict__ qb, bf16* __restrict__ qs,
                                  bf16* __restrict__ kb, bf16* __restrict__ ks)
{
    int i = blockIdx.x * blockDim.x + threadIdx.x;
    int d = i & 63;
    int h = (i >> 6) & 31;
    int s = i >> 11;
    float ratio = 1.2f + (0.6f / 31.0f) * (float)h;
    float t = (float)pos_ids[s] / ratio;
    float inv_freq = exp2f(-(float)d * (13.287712379549449f / 64.0f));
    float f = t * inv_freq;
    float c, sn;
    sincosf(f, &sn, &c);
    size_t base = (size_t)s * HID + h * HD + d;

    float x1 = q[base], x2 = q[base + 64];
    float y0 = x1 * c - x2 * sn;
    float y1 = x2 * c + x1 * sn;
    bf16 t0 = __float2bfloat16(y0);
    bf16 t1 = __float2bfloat16(y1);
    qb[base] = t0;
    qs[base] = __float2bfloat16(y0 - __bfloat162float(t0));
    qb[base + 64] = t1;
    qs[base + 64] = __float2bfloat16(y1 - __bfloat162float(t1));

    x1 = k[base]; x2 = k[base + 64];
    y0 = x1 * c - x2 * sn;
    y1 = x2 * c + x1 * sn;
    t0 = __float2bfloat16(y0);
    t1 = __float2bfloat16(y1);
    kb[base] = t0;
    ks[base] = __float2bfloat16(y0 - __bfloat162float(t0));
    kb[base + 64] = t1;
    ks[base + 64] = __float2bfloat16(y1 - __bfloat162float(t1));
}

// ---------------- probs1: in-place softmax over k<=q ---------------------------
__global__ void probs1_kernel(float* __restrict__ scores)
{
    int q = blockIdx.x, h = blockIdx.y;
    float* row = scores + ((size_t)h * S + q) * S;
    __shared__ float red[256];
    int tid = threadIdx.x;

    float v[8];
    float m = -INFINITY;
#pragma unroll
    for (int j = 0; j < 8; j++) {
        int k = tid + j * 256;
        v[j] = (k <= q) ? row[k] : -INFINITY;
        m = fmaxf(m, v[j]);
    }
    red[tid] = m;
    __syncthreads();
    for (int st = 128; st; st >>= 1) {
        if (tid < st) red[tid] = fmaxf(red[tid], red[tid + st]);
        __syncthreads();
    }
    m = red[0];
    __syncthreads();

    float sum = 0.f;
#pragma unroll
    for (int j = 0; j < 8; j++) {
        v[j] = expf(v[j] - m);
        sum += v[j];
    }
    red[tid] = sum;
    __syncthreads();
    for (int st = 128; st; st >>= 1) {
        if (tid < st) red[tid] += red[tid + st];
        __syncthreads();
    }
    float inv = 1.0f / red[0];
#pragma unroll
    for (int j = 0; j < 8; j++) {
        int k = tid + j * 256;
        if (k <= q) row[k] = v[j] * inv;
    }
}

// ---------------- hh partial sums over q-chunks --------------------------------
__global__ void hh_part_kernel(const float* __restrict__ p1, float* __restrict__ part)
{
    int kb = blockIdx.x, qc = blockIdx.y, h = blockIdx.z;
    if (qc < kb) return;
    int k = kb * 256 + threadIdx.x;
    const float* base = p1 + (size_t)h * S * S;
    int q0 = qc * 256;
    float acc = 0.f;
    for (int q = q0; q < q0 + 256; q++) {
        if (q >= k) acc += base[(size_t)q * S + k];
    }
    part[((size_t)qc * NH + h) * S + k] = acc;
}

__global__ void hh_reduce_kernel(const float* __restrict__ part, float* __restrict__ hh)
{
    int h = blockIdx.y;
    int k = blockIdx.x * 256 + threadIdx.x;
    int kb = k >> 8;
    float acc = 0.f;
    for (int qc = kb; qc < 8; qc++)
        acc += part[((size_t)qc * NH + h) * S + k];
    hh[h * S + k] = acc;
}

// ---------------- per-head top-204 over hh[:SEL]; build key mask ---------------
__global__ void topk_mask_kernel(const float* __restrict__ hh, float* __restrict__ mask)
{
    int h = blockIdx.x;
    int tid = threadIdx.x;
    __shared__ float vals[SEL];
    __shared__ float rmax[256];
    __shared__ int   ridx[256];

    for (int i = tid; i < SEL; i += 256) vals[i] = hh[h * S + i];
    for (int k = tid; k < S; k += 256)  mask[h * S + k] = (k >= SEL) ? 0.f : NEGV;
    __syncthreads();

    for (int it = 0; it < HHSZ; it++) {
        float bm = -INFINITY;
        int bi = SEL;
        for (int i = tid; i < SEL; i += 256) {
            float v = vals[i];
            if (v > bm) { bm = v; bi = i; }
        }
        rmax[tid] = bm;
        ridx[tid] = bi;
        __syncthreads();
        for (int st = 128; st; st >>= 1) {
            if (tid < st) {
                if (rmax[tid + st] > rmax[tid] ||
                    (rmax[tid + st] == rmax[tid] && ridx[tid + st] < ridx[tid])) {
                    rmax[tid] = rmax[tid + st];
                    ridx[tid] = ridx[tid + st];
                }
            }
            __syncthreads();
        }
        if (tid == 0) {
            int kk = ridx[0];
            mask[h * S + kk] = 0.f;
            vals[kk] = -INFINITY;
        }
        __syncthreads();
    }
}

// ---------------- softmax2 = renormalize kept probs1; split bf16 out -----------
__global__ void softmax2_renorm_kernel(const float* __restrict__ p1,
                                       const float* __restrict__ mask,
                                       bf16* __restrict__ pb, bf16* __restrict__ ps)
{
    int q = blockIdx.x, h = blockIdx.y;
    size_t off = ((size_t)h * S + q) * S;
    const float* row = p1 + off;
    const float* mk = mask + h * S;
    __shared__ float red[256];
    int tid = threadIdx.x;
    int tend = ((q >> 7) + 1) << 7;

    float v[8];
    float sum = 0.f;
#pragma unroll
    for (int j = 0; j < 8; j++) {
        int k = tid + j * 256;
        bool kept = (k <= q) && ((mk[k] == 0.f) || (k == q));
        v[j] = kept ? row[k] : 0.f;
        sum += v[j];
    }
    red[tid] = sum;
    __syncthreads();
    for (int st = 128; st; st >>= 1) {
        if (tid < st) red[tid] += red[tid + st];
        __syncthreads();
    }
    float inv = 1.0f / red[0];
#pragma unroll
    for (int j = 0; j < 8; j++) {
        int k = tid + j * 256;
        if (k < tend) {
            float val = v[j] * inv;
            bf16 b = __float2bfloat16(val);
            pb[off + k] = b;
            ps[off + k] = __float2bfloat16(val - __bfloat162float(b));
        }
    }
}

// ---------------- launch --------------------------------------------------------
extern "C" void kernel_launch(void* const* d_in, const int* in_sizes, int n_in,
                              void* d_out, int out_size)
{
    const float* hs = (const float*)d_in[0];
    const float* W0 = (const float*)d_in[1];
    const float* W1 = (const float*)d_in[2];
    const float* W2 = (const float*)d_in[3];
    const float* W3 = (const float*)d_in[4];
    const int* pos = (const int*)d_in[5];
    float* out = (float*)d_out;

    float *q, *k, *scores, *hh, *hhp, *mask;
    bf16 *hsb, *hss, *wb, *ws, *qb, *qs, *kb, *ks, *vb, *vs, *pb, *ps, *ab, *as;
    cudaGetSymbolAddress((void**)&q, g_q);
    cudaGetSymbolAddress((void**)&k, g_k);
    cudaGetSymbolAddress((void**)&scores, g_scores);
    cudaGetSymbolAddress((void**)&hh, g_hh);
    cudaGetSymbolAddress((void**)&hhp, g_hhpart);
    cudaGetSymbolAddress((void**)&mask, g_mask);
    cudaGetSymbolAddress((void**)&hsb, g_hs_b);
    cudaGetSymbolAddress((void**)&hss, g_hs_s);
    cudaGetSymbolAddress((void**)&wb, g_w_b);
    cudaGetSymbolAddress((void**)&ws, g_w_s);
    cudaGetSymbolAddress((void**)&qb, g_qb);
    cudaGetSymbolAddress((void**)&qs, g_qs);
    cudaGetSymbolAddress((void**)&kb, g_kb);
    cudaGetSymbolAddress((void**)&ks, g_ks);
    cudaGetSymbolAddress((void**)&vb, g_vb);
    cudaGetSymbolAddress((void**)&vs, g_vs);
    cudaGetSymbolAddress((void**)&pb, g_pb);
    cudaGetSymbolAddress((void**)&ps, g_ps);
    cudaGetSymbolAddress((void**)&ab, g_ab);
    cudaGetSymbolAddress((void**)&as, g_as);

    const int SM_NT = (2 * (2 * ASZ + 2 * 128 * BNT_ST)) * 4;
    const int SM_NN = (2 * (2 * ASZ + 2 * 32 * BNN_ST)) * 4;
    cudaFuncSetAttribute(gemm_bf3<true, 3, false, false>, cudaFuncAttributeMaxDynamicSharedMemorySize, SM_NT);
    cudaFuncSetAttribute(gemm_bf3<true, 0, false, false>, cudaFuncAttributeMaxDynamicSharedMemorySize, SM_NT);
    cudaFuncSetAttribute(gemm_bf3<true, 0, false, true>,  cudaFuncAttributeMaxDynamicSharedMemorySize, SM_NT);
    cudaFuncSetAttribute(gemm_bf3<false, 2, true, false>, cudaFuncAttributeMaxDynamicSharedMemorySize, SM_NN);

    split_kernel<<<(S * HID) / 2048, 256>>>(hs, hsb, hss);
    splitw_kernel<<<dim3((HID * HID) / 2048, 4), 256>>>(W0, W1, W2, W3, wb, ws);

    // fused Q/K/V projections: blockIdx.z selects weight + destination
    dim3 gqkv(HID / BN, S / BM, 3);
    gemm_bf3<true, 3, false, false><<<gqkv, 256, SM_NT>>>(
        hsb, hss, HID, 0, wb, ws, HID, (size_t)HID * HID,
        q, k, vb, vs, HID, 0, HID, 1.f);

    rope_split_kernel<<<(S * NH * 64) / 256, 256>>>(q, k, pos, qb, qs, kb, ks);

    dim3 gs(136, 1, NH);
    gemm_bf3<true, 0, false, true><<<gs, 256, SM_NT>>>(
        qb, qs, HID, (size_t)HD, kb, ks, HID, (size_t)HD,
        scores, (float*)0, (bf16*)0, (bf16*)0, S, (size_t)S * S, HD, 0.08838834764831845f);

    probs1_kernel<<<dim3(S, NH), 256>>>(scores);
    hh_part_kernel<<<dim3(8, 8, NH), 256>>>(scores, hhp);
    hh_reduce_kernel<<<dim3(8, NH), 256>>>(hhp, hh);
    topk_mask_kernel<<<NH, 256>>>(hh, mask);
    softmax2_renorm_kernel<<<dim3(S, NH), 256>>>(scores, mask, pb, ps);

    dim3 gpv(HD / BN, 16, NH);
    gemm_bf3<false, 2, true, false><<<gpv, 256, SM_NN>>>(
        pb, ps, S, (size_t)S * S, vb, vs, HID, (size_t)HD,
        (float*)0, (float*)0, ab, as, HID, (size_t)HD, S, 1.f);

    gemm_bf3<true, 0, false, false><<<dim3(HID / BN, S / BM, 1), 256, SM_NT>>>(
        ab, as, HID, 0, wb + 3 * (size_t)HID * HID, ws + 3 * (size_t)HID * HID, HID, 0,
        out, (float*)0, (bf16*)0, (bf16*)0, HID, 0, HID, 1.f);
}

// round 15
// speedup vs baseline: 1.1528x; 1.0466x over previous
#include <cuda_runtime.h>
#include <cuda_bf16.h>
#include <math.h>

#define S    2048
#define NH   32
#define HD   128
#define HID  4096
#define NEGV -1000000000.0f
#define HHSZ 204
#define RECENT 204
#define SEL  (S - RECENT)
#define NKEEP 408
#define NKP   416   // padded kept count (multiple of 32)

typedef __nv_bfloat16 bf16;

// ---------------- scratch ----------------------------------------------------
__device__ float g_q[(size_t)S * HID];       // q fp32, then reused as attn fp32
__device__ float g_k[(size_t)S * HID];
__device__ float g_scores[(size_t)NH * S * S];
__device__ float g_hh[NH * S];
__device__ float g_hhpart[8 * NH * S];
__device__ float g_mask[NH * S];
__device__ float g_pdiag[NH * S];
__device__ int   g_idx[NH * NKP];

__device__ bf16 g_hs_b[(size_t)S * HID],  g_hs_s[(size_t)S * HID];
__device__ bf16 g_w_b[4][(size_t)HID * HID], g_w_s[4][(size_t)HID * HID];
__device__ bf16 g_qb[(size_t)S * HID], g_qs[(size_t)S * HID];
__device__ bf16 g_kb[(size_t)S * HID], g_ks[(size_t)S * HID];
__device__ bf16 g_vb[(size_t)S * HID], g_vs[(size_t)S * HID];
__device__ bf16 g_pcb[(size_t)NH * S * NKP], g_pcs[(size_t)NH * S * NKP];
__device__ bf16 g_vcb[(size_t)NH * NKP * HD], g_vcs[(size_t)NH * NKP * HD];
__device__ bf16 g_ab[(size_t)S * HID], g_as[(size_t)S * HID];

// ---------------- HMMA helpers (proven) --------------------------------------
__device__ __forceinline__ void mma_bf16(float c[4],
    unsigned a0, unsigned a1, unsigned a2, unsigned a3, unsigned b0, unsigned b1)
{
    asm volatile(
        "mma.sync.aligned.m16n8k16.row.col.f32.bf16.bf16.f32 "
        "{%0,%1,%2,%3}, {%4,%5,%6,%7}, {%8,%9}, {%0,%1,%2,%3};"
        : "+f"(c[0]), "+f"(c[1]), "+f"(c[2]), "+f"(c[3])
        : "r"(a0), "r"(a1), "r"(a2), "r"(a3), "r"(b0), "r"(b1));
}
__device__ __forceinline__ void ldsm_x4(unsigned r[4], unsigned addr)
{
    asm volatile("ldmatrix.sync.aligned.m8n8.x4.shared.b16 {%0,%1,%2,%3}, [%4];"
        : "=r"(r[0]), "=r"(r[1]), "=r"(r[2]), "=r"(r[3]) : "r"(addr));
}
__device__ __forceinline__ void ldsm_x4t(unsigned r[4], unsigned addr)
{
    asm volatile("ldmatrix.sync.aligned.m8n8.x4.trans.shared.b16 {%0,%1,%2,%3}, [%4];"
        : "=r"(r[0]), "=r"(r[1]), "=r"(r[2]), "=r"(r[3]) : "r"(addr));
}
__device__ __forceinline__ void cp16(unsigned dst, const void* src)
{
    asm volatile("cp.async.cg.shared.global [%0], [%1], 16;" :: "r"(dst), "l"(src));
}
__device__ __forceinline__ void cp_commit() { asm volatile("cp.async.commit_group;" ::: "memory"); }
__device__ __forceinline__ void cp_wait0() { asm volatile("cp.async.wait_group 0;" ::: "memory"); }

// term-major MMA issue for one nj
#define MMA_NJ_BLOCK(accA, accB, accA2, accB2, abf, asf, bbf, bsf) do { \
    mma_bf16(accA,  (abf)[0][0], (abf)[0][1], (abf)[0][2], (abf)[0][3], (bsf)[0], (bsf)[1]); \
    mma_bf16(accB,  (abf)[0][0], (abf)[0][1], (abf)[0][2], (abf)[0][3], (bsf)[2], (bsf)[3]); \
    mma_bf16(accA2, (abf)[1][0], (abf)[1][1], (abf)[1][2], (abf)[1][3], (bsf)[0], (bsf)[1]); \
    mma_bf16(accB2, (abf)[1][0], (abf)[1][1], (abf)[1][2], (abf)[1][3], (bsf)[2], (bsf)[3]); \
    mma_bf16(accA,  (asf)[0][0], (asf)[0][1], (asf)[0][2], (asf)[0][3], (bbf)[0], (bbf)[1]); \
    mma_bf16(accB,  (asf)[0][0], (asf)[0][1], (asf)[0][2], (asf)[0][3], (bbf)[2], (bbf)[3]); \
    mma_bf16(accA2, (asf)[1][0], (asf)[1][1], (asf)[1][2], (asf)[1][3], (bbf)[0], (bbf)[1]); \
    mma_bf16(accB2, (asf)[1][0], (asf)[1][1], (asf)[1][2], (asf)[1][3], (bbf)[2], (bbf)[3]); \
    mma_bf16(accA,  (abf)[0][0], (abf)[0][1], (abf)[0][2], (abf)[0][3], (bbf)[0], (bbf)[1]); \
    mma_bf16(accB,  (abf)[0][0], (abf)[0][1], (abf)[0][2], (abf)[0][3], (bbf)[2], (bbf)[3]); \
    mma_bf16(accA2, (abf)[1][0], (abf)[1][1], (abf)[1][2], (abf)[1][3], (bbf)[0], (bbf)[1]); \
    mma_bf16(accB2, (abf)[1][0], (abf)[1][1], (abf)[1][2], (abf)[1][3], (bbf)[2], (bbf)[3]); \
} while (0)

// ================= HMMA bf16x3 GEMM 128x128, single-barrier 2-stage ==========
// EPI: 0 fp32 store, 2 split-bf16 store, 3 QKV-fused (bz selects dest/format)
#define BM 128
#define BN 128
#define BK 32
#define A_ST 20
#define ASZ  (128 * A_ST)
#define BNT_ST 20
#define BNN_ST 68

template <bool NT, int EPI, bool TRUNC, bool LOWER>
__global__ __launch_bounds__(256, 2) void gemm_bf3(
    const bf16* __restrict__ Agb, const bf16* __restrict__ Ags, int lda, size_t sA,
    const bf16* __restrict__ Bgb, const bf16* __restrict__ Bgs, int ldb, size_t sB,
    float* __restrict__ Cf, float* __restrict__ Cf2,
    bf16* __restrict__ Cb, bf16* __restrict__ Cs,
    int ldc, size_t sC, int K, float alpha)
{
    const int bz = blockIdx.z;
    Agb += (size_t)bz * sA; Ags += (size_t)bz * sA;
    Bgb += (size_t)bz * sB; Bgs += (size_t)bz * sB;
    if (EPI == 2) { Cb += (size_t)bz * sC; Cs += (size_t)bz * sC; }
    else if (EPI == 0) { Cf += (size_t)bz * sC; }

    int bm, bn;
    if (LOWER) {
        int idx = blockIdx.x;
        int r = (int)((sqrtf(8.f * (float)idx + 1.f) - 1.f) * 0.5f);
        while ((r + 1) * (r + 2) / 2 <= idx) r++;
        while (r * (r + 1) / 2 > idx) r--;
        bm = r * BM;
        bn = (idx - r * (r + 1) / 2) * BN;
    } else if (TRUNC) {
        bm = (gridDim.y - 1 - blockIdx.y) * BM;
        bn = blockIdx.x * BN;
    } else {
        bm = blockIdx.y * BM;
        bn = blockIdx.x * BN;
    }

    const int tid  = threadIdx.x;
    const int wid  = tid >> 5;
    const int lane = tid & 31;
    const int g  = lane >> 2;
    const int tg = lane & 3;
    const int wm = (wid & 3) * 32;
    const int wn = (wid >> 2) * 64;

    extern __shared__ unsigned sm[];
    const unsigned smb = (unsigned)__cvta_generic_to_shared(sm);
    const int BSZ = NT ? (128 * BNT_ST) : (32 * BNN_ST);
    const int STG = 2 * ASZ + 2 * BSZ;
    const int OFF_AB = 0, OFF_AS = ASZ, OFF_BB = 2 * ASZ, OFF_BS = 2 * ASZ + BSZ;

    const int kend = TRUNC ? (bm + BM) : K;
    const int T = kend / BK;

    float acc[2][8][4];
#pragma unroll
    for (int i = 0; i < 2; i++)
#pragma unroll
        for (int j = 0; j < 8; j++)
#pragma unroll
            for (int t2 = 0; t2 < 4; t2++) acc[i][j][t2] = 0.f;

    const int a_row = (lane & 15);
    const int a_hi  = (lane >> 4) << 2;
    const int bnt_row = (lane & 7) + ((lane >> 4) & 1) * 8;
    const int bnt_hi  = ((lane >> 3) & 1) * 4;
    const int bnn_krow = (lane & 15);
    const int bnn_nhi  = ((lane >> 4) & 1) * 8;

    // prefetch tile 0
    {
        const int so = 0;
#pragma unroll
        for (int r = 0; r < 2; r++) {
            int s = tid + r * 256;
            int arow = s >> 2, aseg = s & 3;
            size_t aoff = (size_t)(bm + arow) * lda + aseg * 8;
            unsigned adst = smb + (so + OFF_AB + arow * A_ST + aseg * 4) * 4;
            cp16(adst, Agb + aoff);
            cp16(adst + ASZ * 4, Ags + aoff);
            if (NT) {
                size_t boff = (size_t)(bn + arow) * ldb + aseg * 8;
                unsigned bdst = smb + (so + OFF_BB + arow * BNT_ST + aseg * 4) * 4;
                cp16(bdst, Bgb + boff);
                cp16(bdst + BSZ * 4, Bgs + boff);
            } else {
                int krow = s >> 4, nseg = s & 15;
                size_t boff = (size_t)krow * ldb + bn + nseg * 8;
                unsigned bdst = smb + (so + OFF_BB + krow * BNN_ST + nseg * 4) * 4;
                cp16(bdst, Bgb + boff);
                cp16(bdst + BSZ * 4, Bgs + boff);
            }
        }
        cp_commit();
    }

    for (int t = 0; t < T; t++) {
        cp_wait0();
        __syncthreads();

        if (t + 1 < T) {
            const int so = ((t + 1) & 1) * STG;
            const int k0 = (t + 1) * BK;
#pragma unroll
            for (int r = 0; r < 2; r++) {
                int s = tid + r * 256;
                int arow = s >> 2, aseg = s & 3;
                size_t aoff = (size_t)(bm + arow) * lda + k0 + aseg * 8;
                unsigned adst = smb + (so + OFF_AB + arow * A_ST + aseg * 4) * 4;
                cp16(adst, Agb + aoff);
                cp16(adst + ASZ * 4, Ags + aoff);
                if (NT) {
                    size_t boff = (size_t)(bn + arow) * ldb + k0 + aseg * 8;
                    unsigned bdst = smb + (so + OFF_BB + arow * BNT_ST + aseg * 4) * 4;
                    cp16(bdst, Bgb + boff);
                    cp16(bdst + BSZ * 4, Bgs + boff);
                } else {
                    int krow = s >> 4, nseg = s & 15;
                    size_t boff = (size_t)(k0 + krow) * ldb + bn + nseg * 8;
                    unsigned bdst = smb + (so + OFF_BB + krow * BNN_ST + nseg * 4) * 4;
                    cp16(bdst, Bgb + boff);
                    cp16(bdst + BSZ * 4, Bgs + boff);
                }
            }
            cp_commit();
        }

        const int so = (t & 1) * STG;
#pragma unroll
        for (int kk = 0; kk < 2; kk++) {
            unsigned ab[2][4], as_[2][4];
#pragma unroll
            for (int mi = 0; mi < 2; mi++) {
                int idx = (wm + mi * 16 + a_row) * A_ST + kk * 8 + a_hi;
                ldsm_x4(ab[mi],  smb + (so + OFF_AB + idx) * 4);
                ldsm_x4(as_[mi], smb + (so + OFF_AS + idx) * 4);
            }
#pragma unroll
            for (int nj = 0; nj < 4; nj++) {
                unsigned bb[4], bs[4];
                if (NT) {
                    int idx = (wn + nj * 16 + bnt_row) * BNT_ST + kk * 8 + bnt_hi;
                    ldsm_x4(bb, smb + (so + OFF_BB + idx) * 4);
                    ldsm_x4(bs, smb + (so + OFF_BS + idx) * 4);
                } else {
                    int idx = (kk * 16 + bnn_krow) * BNN_ST + ((wn + nj * 16 + bnn_nhi) >> 1);
                    ldsm_x4t(bb, smb + (so + OFF_BB + idx) * 4);
                    ldsm_x4t(bs, smb + (so + OFF_BS + idx) * 4);
                }
                MMA_NJ_BLOCK(acc[0][2 * nj], acc[0][2 * nj + 1],
                             acc[1][2 * nj], acc[1][2 * nj + 1], ab, as_, bb, bs);
            }
        }
    }

    const bool split_out = (EPI == 2) || (EPI == 3 && bz == 2);
    float* fout = (EPI == 3) ? ((bz == 1) ? Cf2 : Cf) : Cf;

#pragma unroll
    for (int mi = 0; mi < 2; mi++) {
#pragma unroll
        for (int ni = 0; ni < 8; ni++) {
            int r0 = bm + wm + mi * 16 + g;
            int c0 = bn + wn + ni * 8 + tg * 2;
            float v0 = acc[mi][ni][0] * alpha;
            float v1 = acc[mi][ni][1] * alpha;
            float v2 = acc[mi][ni][2] * alpha;
            float v3 = acc[mi][ni][3] * alpha;
            if (split_out) {
                bf16 b0 = __float2bfloat16(v0), b1 = __float2bfloat16(v1);
                bf16 b2 = __float2bfloat16(v2), b3 = __float2bfloat16(v3);
                __nv_bfloat162 pb0, pb1, ps0, ps1;
                pb0.x = b0; pb0.y = b1; pb1.x = b2; pb1.y = b3;
                ps0.x = __float2bfloat16(v0 - __bfloat162float(b0));
                ps0.y = __float2bfloat16(v1 - __bfloat162float(b1));
                ps1.x = __float2bfloat16(v2 - __bfloat162float(b2));
                ps1.y = __float2bfloat16(v3 - __bfloat162float(b3));
                *(__nv_bfloat162*)(Cb + (size_t)r0 * ldc + c0)       = pb0;
                *(__nv_bfloat162*)(Cb + (size_t)(r0 + 8) * ldc + c0) = pb1;
                *(__nv_bfloat162*)(Cs + (size_t)r0 * ldc + c0)       = ps0;
                *(__nv_bfloat162*)(Cs + (size_t)(r0 + 8) * ldc + c0) = ps1;
            } else {
                *(float2*)(fout + (size_t)r0 * ldc + c0)       = make_float2(v0, v1);
                *(float2*)(fout + (size_t)(r0 + 8) * ldc + c0) = make_float2(v2, v3);
            }
        }
    }
}

// ---------------- split fp32 -> bf16 big/small --------------------------------
__device__ __forceinline__ void split4(const float4 v, bf16* xb, bf16* xs, size_t i)
{
    bf16 b0 = __float2bfloat16(v.x), b1 = __float2bfloat16(v.y);
    bf16 b2 = __float2bfloat16(v.z), b3 = __float2bfloat16(v.w);
    __nv_bfloat162 pb0, pb1, ps0, ps1;
    pb0.x = b0; pb0.y = b1; pb1.x = b2; pb1.y = b3;
    ps0.x = __float2bfloat16(v.x - __bfloat162float(b0));
    ps0.y = __float2bfloat16(v.y - __bfloat162float(b1));
    ps1.x = __float2bfloat16(v.z - __bfloat162float(b2));
    ps1.y = __float2bfloat16(v.w - __bfloat162float(b3));
    *(__nv_bfloat162*)(xb + i)     = pb0;
    *(__nv_bfloat162*)(xb + i + 2) = pb1;
    *(__nv_bfloat162*)(xs + i)     = ps0;
    *(__nv_bfloat162*)(xs + i + 2) = ps1;
}

__global__ void split_kernel(const float* __restrict__ x,
                             bf16* __restrict__ xb, bf16* __restrict__ xs)
{
    size_t i = ((size_t)blockIdx.x * 256 + threadIdx.x) * 8;
    float4 v0 = *(const float4*)(x + i);
    float4 v1 = *(const float4*)(x + i + 4);
    split4(v0, xb, xs, i);
    split4(v1, xb, xs, i + 4);
}

__global__ void splitw_kernel(const float* __restrict__ W0, const float* __restrict__ W1,
                              const float* __restrict__ W2, const float* __restrict__ W3,
                              bf16* __restrict__ xb, bf16* __restrict__ xs)
{
    int w = blockIdx.y;
    const float* x = (w == 0) ? W0 : (w == 1) ? W1 : (w == 2) ? W2 : W3;
    size_t base = (size_t)w * HID * HID;
    size_t i = ((size_t)blockIdx.x * 256 + threadIdx.x) * 8;
    float4 v0 = *(const float4*)(x + i);
    float4 v1 = *(const float4*)(x + i + 4);
    split4(v0, xb + base, xs + base, i);
    split4(v1, xb + base, xs + base, i + 4);
}

// ---------------- MsPoE rotary -> split bf16 ----------------------------------
__global__ void rope_split_kernel(const float* __restrict__ q, const float* __restrict__ k,
                                  const int* __restrict__ pos_ids,
                                  bf16* __restrict__ qb, bf16* __restrict__ qs,
                                  bf16* __restrict__ kb, bf16* __restrict__ ks)
{
    int i = blockIdx.x * blockDim.x + threadIdx.x;
    int d = i & 63;
    int h = (i >> 6) & 31;
    int s = i >> 11;
    float ratio = 1.2f + (0.6f / 31.0f) * (float)h;
    float t = (float)pos_ids[s] / ratio;
    float inv_freq = exp2f(-(float)d * (13.287712379549449f / 64.0f));
    float f = t * inv_freq;
    float c, sn;
    sincosf(f, &sn, &c);
    size_t base = (size_t)s * HID + h * HD + d;

    float x1 = q[base], x2 = q[base + 64];
    float y0 = x1 * c - x2 * sn;
    float y1 = x2 * c + x1 * sn;
    bf16 t0 = __float2bfloat16(y0);
    bf16 t1 = __float2bfloat16(y1);
    qb[base] = t0;
    qs[base] = __float2bfloat16(y0 - __bfloat162float(t0));
    qb[base + 64] = t1;
    qs[base + 64] = __float2bfloat16(y1 - __bfloat162float(t1));

    x1 = k[base]; x2 = k[base + 64];
    y0 = x1 * c - x2 * sn;
    y1 = x2 * c + x1 * sn;
    t0 = __float2bfloat16(y0);
    t1 = __float2bfloat16(y1);
    kb[base] = t0;
    ks[base] = __float2bfloat16(y0 - __bfloat162float(t0));
    kb[base + 64] = t1;
    ks[base + 64] = __float2bfloat16(y1 - __bfloat162float(t1));
}

// ---------------- probs1: in-place softmax over k<=q ---------------------------
__global__ void probs1_kernel(float* __restrict__ scores)
{
    int q = blockIdx.x, h = blockIdx.y;
    float* row = scores + ((size_t)h * S + q) * S;
    __shared__ float red[256];
    int tid = threadIdx.x;

    float v[8];
    float m = -INFINITY;
#pragma unroll
    for (int j = 0; j < 8; j++) {
        int k = tid + j * 256;
        v[j] = (k <= q) ? row[k] : -INFINITY;
        m = fmaxf(m, v[j]);
    }
    red[tid] = m;
    __syncthreads();
    for (int st = 128; st; st >>= 1) {
        if (tid < st) red[tid] = fmaxf(red[tid], red[tid + st]);
        __syncthreads();
    }
    m = red[0];
    __syncthreads();

    float sum = 0.f;
#pragma unroll
    for (int j = 0; j < 8; j++) {
        v[j] = expf(v[j] - m);
        sum += v[j];
    }
    red[tid] = sum;
    __syncthreads();
    for (int st = 128; st; st >>= 1) {
        if (tid < st) red[tid] += red[tid + st];
        __syncthreads();
    }
    float inv = 1.0f / red[0];
#pragma unroll
    for (int j = 0; j < 8; j++) {
        int k = tid + j * 256;
        if (k <= q) row[k] = v[j] * inv;
    }
}

// ---------------- hh partial sums over q-chunks --------------------------------
__global__ void hh_part_kernel(const float* __restrict__ p1, float* __restrict__ part)
{
    int kb = blockIdx.x, qc = blockIdx.y, h = blockIdx.z;
    if (qc < kb) return;
    int k = kb * 256 + threadIdx.x;
    const float* base = p1 + (size_t)h * S * S;
    int q0 = qc * 256;
    float acc = 0.f;
    for (int q = q0; q < q0 + 256; q++) {
        if (q >= k) acc += base[(size_t)q * S + k];
    }
    part[((size_t)qc * NH + h) * S + k] = acc;
}

__global__ void hh_reduce_kernel(const float* __restrict__ part, float* __restrict__ hh)
{
    int h = blockIdx.y;
    int k = blockIdx.x * 256 + threadIdx.x;
    int kb = k >> 8;
    float acc = 0.f;
    for (int qc = kb; qc < 8; qc++)
        acc += part[((size_t)qc * NH + h) * S + k];
    hh[h * S + k] = acc;
}

// ---------------- per-head top-204 over hh[:SEL]; build key mask ---------------
__global__ void topk_mask_kernel(const float* __restrict__ hh, float* __restrict__ mask)
{
    int h = blockIdx.x;
    int tid = threadIdx.x;
    __shared__ float vals[SEL];
    __shared__ float rmax[256];
    __shared__ int   ridx[256];

    for (int i = tid; i < SEL; i += 256) vals[i] = hh[h * S + i];
    for (int k = tid; k < S; k += 256)  mask[h * S + k] = (k >= SEL) ? 0.f : NEGV;
    __syncthreads();

    for (int it = 0; it < HHSZ; it++) {
        float bm = -INFINITY;
        int bi = SEL;
        for (int i = tid; i < SEL; i += 256) {
            float v = vals[i];
            if (v > bm) { bm = v; bi = i; }
        }
        rmax[tid] = bm;
        ridx[tid] = bi;
        __syncthreads();
        for (int st = 128; st; st >>= 1) {
            if (tid < st) {
                if (rmax[tid + st] > rmax[tid] ||
                    (rmax[tid + st] == rmax[tid] && ridx[tid + st] < ridx[tid])) {
                    rmax[tid] = rmax[tid + st];
                    ridx[tid] = ridx[tid + st];
                }
            }
            __syncthreads();
        }
        if (tid == 0) {
            int kk = ridx[0];
            mask[h * S + kk] = 0.f;
            vals[kk] = -INFINITY;
        }
        __syncthreads();
    }
}

// ---------------- collect kept indices (sorted ascending) ----------------------
__global__ void collect_idx_kernel(const float* __restrict__ mask, int* __restrict__ idx)
{
    int h = blockIdx.x, tid = threadIdx.x;
    __shared__ int cnt[256];
    int local[8];
    int c = 0;
#pragma unroll
    for (int i = 0; i < 8; i++) {
        int k = tid * 8 + i;
        if (mask[h * S + k] == 0.f) local[c++] = k;
    }
    cnt[tid] = c;
    __syncthreads();
    for (int off = 1; off < 256; off <<= 1) {
        int v = (tid >= off) ? cnt[tid - off] : 0;
        __syncthreads();
        cnt[tid] += v;
        __syncthreads();
    }
    int base = cnt[tid] - c;
    for (int j = 0; j < c; j++) idx[h * NKP + base + j] = local[j];
    if (tid < NKP - NKEEP) idx[h * NKP + NKEEP + tid] = -1;
}

// ---------------- gather compacted V -------------------------------------------
__global__ void vc_gather_kernel(const int* __restrict__ idx,
                                 const bf16* __restrict__ vb, const bf16* __restrict__ vs,
                                 bf16* __restrict__ vcb, bf16* __restrict__ vcs)
{
    int j = blockIdx.x, h = blockIdx.y, d = threadIdx.x;
    int i = idx[h * NKP + j];
    size_t o = ((size_t)h * NKP + j) * HD + d;
    bf16 z = __float2bfloat16(0.f);
    vcb[o] = (i >= 0) ? vb[(size_t)i * HID + h * HD + d] : z;
    vcs[o] = (i >= 0) ? vs[(size_t)i * HID + h * HD + d] : z;
}

// ---------------- softmax2: renormalize + compact kept columns ------------------
__global__ void softmax2_compact_kernel(const float* __restrict__ p1,
                                        const float* __restrict__ mask,
                                        const int* __restrict__ idx,
                                        bf16* __restrict__ pcb, bf16* __restrict__ pcs,
                                        float* __restrict__ pdiag)
{
    int q = blockIdx.x, h = blockIdx.y, tid = threadIdx.x;
    const float* row = p1 + ((size_t)h * S + q) * S;
    __shared__ int sidx[NKP];
    __shared__ float red[256];
    for (int j = tid; j < NKP; j += 256) sidx[j] = idx[h * NKP + j];
    __syncthreads();

    float v[2];
    float sum = 0.f;
#pragma unroll
    for (int r = 0; r < 2; r++) {
        int j = tid + r * 256;
        float p = 0.f;
        if (j < NKP) {
            int ij = sidx[j];
            if (ij >= 0 && ij <= q) p = row[ij];
        }
        v[r] = p;
        sum += p;
    }
    bool kept_q = (mask[h * S + q] == 0.f);
    float pd = kept_q ? 0.f : row[q];

    red[tid] = sum;
    __syncthreads();
    for (int st = 128; st; st >>= 1) {
        if (tid < st) red[tid] += red[tid + st];
        __syncthreads();
    }
    float inv = 1.0f / (red[0] + pd);

    size_t off = ((size_t)h * S + q) * NKP;
#pragma unroll
    for (int r = 0; r < 2; r++) {
        int j = tid + r * 256;
        if (j < NKP) {
            float val = v[r] * inv;
            bf16 b = __float2bfloat16(val);
            pcb[off + j] = b;
            pcs[off + j] = __float2bfloat16(val - __bfloat162float(b));
        }
    }
    if (tid == 0) pdiag[h * S + q] = kept_q ? 0.f : pd * inv;
}

// ---------------- add diagonal term + split attn to bf16 ------------------------
__global__ void diag_split_kernel(const float* __restrict__ attn,
                                  const float* __restrict__ pdiag,
                                  const bf16* __restrict__ vb, const bf16* __restrict__ vs,
                                  bf16* __restrict__ ab, bf16* __restrict__ as_)
{
    size_t e = ((size_t)blockIdx.x * 256 + threadIdx.x) * 4;
    int q = (int)(e / HID);
    int col = (int)(e % HID);
    int h = col >> 7;
    float pdv = pdiag[h * S + q];
    float4 a = *(const float4*)(attn + e);
    float4 o;
    o.x = a.x + pdv * (__bfloat162float(vb[e + 0]) + __bfloat162float(vs[e + 0]));
    o.y = a.y + pdv * (__bfloat162float(vb[e + 1]) + __bfloat162float(vs[e + 1]));
    o.z = a.z + pdv * (__bfloat162float(vb[e + 2]) + __bfloat162float(vs[e + 2]));
    o.w = a.w + pdv * (__bfloat162float(vb[e + 3]) + __bfloat162float(vs[e + 3]));
    split4(o, ab, as_, e);
}

// ---------------- launch --------------------------------------------------------
extern "C" void kernel_launch(void* const* d_in, const int* in_sizes, int n_in,
                              void* d_out, int out_size)
{
    const float* hs = (const float*)d_in[0];
    const float* W0 = (const float*)d_in[1];
    const float* W1 = (const float*)d_in[2];
    const float* W2 = (const float*)d_in[3];
    const float* W3 = (const float*)d_in[4];
    const int* pos = (const int*)d_in[5];
    float* out = (float*)d_out;

    float *q, *k, *scores, *hh, *hhp, *mask, *pdiag;
    int* idx;
    bf16 *hsb, *hss, *wb, *ws, *qb, *qs, *kb, *ks, *vb, *vs;
    bf16 *pcb, *pcs, *vcb, *vcs, *ab, *as;
    cudaGetSymbolAddress((void**)&q, g_q);
    cudaGetSymbolAddress((void**)&k, g_k);
    cudaGetSymbolAddress((void**)&scores, g_scores);
    cudaGetSymbolAddress((void**)&hh, g_hh);
    cudaGetSymbolAddress((void**)&hhp, g_hhpart);
    cudaGetSymbolAddress((void**)&mask, g_mask);
    cudaGetSymbolAddress((void**)&pdiag, g_pdiag);
    cudaGetSymbolAddress((void**)&idx, g_idx);
    cudaGetSymbolAddress((void**)&hsb, g_hs_b);
    cudaGetSymbolAddress((void**)&hss, g_hs_s);
    cudaGetSymbolAddress((void**)&wb, g_w_b);
    cudaGetSymbolAddress((void**)&ws, g_w_s);
    cudaGetSymbolAddress((void**)&qb, g_qb);
    cudaGetSymbolAddress((void**)&qs, g_qs);
    cudaGetSymbolAddress((void**)&kb, g_kb);
    cudaGetSymbolAddress((void**)&ks, g_ks);
    cudaGetSymbolAddress((void**)&vb, g_vb);
    cudaGetSymbolAddress((void**)&vs, g_vs);
    cudaGetSymbolAddress((void**)&pcb, g_pcb);
    cudaGetSymbolAddress((void**)&pcs, g_pcs);
    cudaGetSymbolAddress((void**)&vcb, g_vcb);
    cudaGetSymbolAddress((void**)&vcs, g_vcs);
    cudaGetSymbolAddress((void**)&ab, g_ab);
    cudaGetSymbolAddress((void**)&as, g_as);

    const int SM_NT = (2 * (2 * ASZ + 2 * 128 * BNT_ST)) * 4;
    const int SM_NN = (2 * (2 * ASZ + 2 * 32 * BNN_ST)) * 4;
    cudaFuncSetAttribute(gemm_bf3<true, 3, false, false>, cudaFuncAttributeMaxDynamicSharedMemorySize, SM_NT);
    cudaFuncSetAttribute(gemm_bf3<true, 0, false, false>, cudaFuncAttributeMaxDynamicSharedMemorySize, SM_NT);
    cudaFuncSetAttribute(gemm_bf3<true, 0, false, true>,  cudaFuncAttributeMaxDynamicSharedMemorySize, SM_NT);
    cudaFuncSetAttribute(gemm_bf3<false, 0, false, false>, cudaFuncAttributeMaxDynamicSharedMemorySize, SM_NN);

    split_kernel<<<(S * HID) / 2048, 256>>>(hs, hsb, hss);
    splitw_kernel<<<dim3((HID * HID) / 2048, 4), 256>>>(W0, W1, W2, W3, wb, ws);

    // fused Q/K/V projections
    dim3 gqkv(HID / BN, S / BM, 3);
    gemm_bf3<true, 3, false, false><<<gqkv, 256, SM_NT>>>(
        hsb, hss, HID, 0, wb, ws, HID, (size_t)HID * HID,
        q, k, vb, vs, HID, 0, HID, 1.f);

    rope_split_kernel<<<(S * NH * 64) / 256, 256>>>(q, k, pos, qb, qs, kb, ks);

    // QK^T lower-triangle tiles only
    dim3 gs(136, 1, NH);
    gemm_bf3<true, 0, false, true><<<gs, 256, SM_NT>>>(
        qb, qs, HID, (size_t)HD, kb, ks, HID, (size_t)HD,
        scores, (float*)0, (bf16*)0, (bf16*)0, S, (size_t)S * S, HD, 0.08838834764831845f);

    probs1_kernel<<<dim3(S, NH), 256>>>(scores);
    hh_part_kernel<<<dim3(8, 8, NH), 256>>>(scores, hhp);
    hh_reduce_kernel<<<dim3(8, NH), 256>>>(hhp, hh);
    topk_mask_kernel<<<NH, 256>>>(hh, mask);

    // sparse PV path: collect kept indices, gather V, compact renormalized probs
    collect_idx_kernel<<<NH, 256>>>(mask, idx);
    vc_gather_kernel<<<dim3(NKP, NH), 128>>>(idx, vb, vs, vcb, vcs);
    softmax2_compact_kernel<<<dim3(S, NH), 256>>>(scores, mask, idx, pcb, pcs, pdiag);

    // PV: attn_fp32 = Pc @ Vc (uniform K=416), write into g_q (free after rope)
    dim3 gpv(1, S / BM, NH);
    gemm_bf3<false, 0, false, false><<<gpv, 256, SM_NN>>>(
        pcb, pcs, NKP, (size_t)S * NKP, vcb, vcs, HD, (size_t)NKP * HD,
        q, (float*)0, (bf16*)0, (bf16*)0, HID, (size_t)HD, NKP, 1.f);

    // add diagonal term + split attn
    diag_split_kernel<<<(S * HID) / 1024, 256>>>(q, pdiag, vb, vs, ab, as);

    // O projection
    gemm_bf3<true, 0, false, false><<<dim3(HID / BN, S / BM, 1), 256, SM_NT>>>(
        ab, as, HID, 0, wb + 3 * (size_t)HID * HID, ws + 3 * (size_t)HID * HID, HID, 0,
        out, (float*)0, (bf16*)0, (bf16*)0, HID, 0, HID, 1.f);
}

// round 16
// speedup vs baseline: 1.1732x; 1.0178x over previous
#include <cuda_runtime.h>
#include <cuda_bf16.h>
#include <math.h>

#define S    2048
#define NH   32
#define HD   128
#define HID  4096
#define NEGV -1000000000.0f
#define HHSZ 204
#define RECENT 204
#define SEL  (S - RECENT)
#define NKEEP 408
#define NKP   416   // padded kept count (multiple of 32)

typedef __nv_bfloat16 bf16;

// ---------------- scratch ----------------------------------------------------
__device__ float g_q[(size_t)S * HID];       // q fp32, then reused as attn fp32
__device__ float g_k[(size_t)S * HID];
__device__ float g_scores[(size_t)NH * S * S];
__device__ float g_hh[NH * S];
__device__ float g_hhpart[8 * NH * S];
__device__ float g_mask[NH * S];
__device__ float g_pdiag[NH * S];
__device__ int   g_idx[NH * NKP];

__device__ bf16 g_hs_b[(size_t)S * HID],  g_hs_s[(size_t)S * HID];
__device__ bf16 g_w_b[4][(size_t)HID * HID], g_w_s[4][(size_t)HID * HID];
__device__ bf16 g_qb[(size_t)S * HID], g_qs[(size_t)S * HID];
__device__ bf16 g_kb[(size_t)S * HID], g_ks[(size_t)S * HID];
__device__ bf16 g_vb[(size_t)S * HID], g_vs[(size_t)S * HID];
__device__ bf16 g_pcb[(size_t)NH * S * NKP], g_pcs[(size_t)NH * S * NKP];
__device__ bf16 g_vcb[(size_t)NH * NKP * HD], g_vcs[(size_t)NH * NKP * HD];
__device__ bf16 g_ab[(size_t)S * HID], g_as[(size_t)S * HID];

// ---------------- HMMA helpers (proven) --------------------------------------
__device__ __forceinline__ void mma_bf16(float c[4],
    unsigned a0, unsigned a1, unsigned a2, unsigned a3, unsigned b0, unsigned b1)
{
    asm volatile(
        "mma.sync.aligned.m16n8k16.row.col.f32.bf16.bf16.f32 "
        "{%0,%1,%2,%3}, {%4,%5,%6,%7}, {%8,%9}, {%0,%1,%2,%3};"
        : "+f"(c[0]), "+f"(c[1]), "+f"(c[2]), "+f"(c[3])
        : "r"(a0), "r"(a1), "r"(a2), "r"(a3), "r"(b0), "r"(b1));
}
__device__ __forceinline__ void ldsm_x4(unsigned r[4], unsigned addr)
{
    asm volatile("ldmatrix.sync.aligned.m8n8.x4.shared.b16 {%0,%1,%2,%3}, [%4];"
        : "=r"(r[0]), "=r"(r[1]), "=r"(r[2]), "=r"(r[3]) : "r"(addr));
}
__device__ __forceinline__ void ldsm_x4t(unsigned r[4], unsigned addr)
{
    asm volatile("ldmatrix.sync.aligned.m8n8.x4.trans.shared.b16 {%0,%1,%2,%3}, [%4];"
        : "=r"(r[0]), "=r"(r[1]), "=r"(r[2]), "=r"(r[3]) : "r"(addr));
}
__device__ __forceinline__ void cp16(unsigned dst, const void* src)
{
    asm volatile("cp.async.cg.shared.global [%0], [%1], 16;" :: "r"(dst), "l"(src));
}
__device__ __forceinline__ void cp_commit() { asm volatile("cp.async.commit_group;" ::: "memory"); }
__device__ __forceinline__ void cp_wait0() { asm volatile("cp.async.wait_group 0;" ::: "memory"); }

// term-major MMA issue for one nj
#define MMA_NJ_BLOCK(accA, accB, accA2, accB2, abf, asf, bbf, bsf) do { \
    mma_bf16(accA,  (abf)[0][0], (abf)[0][1], (abf)[0][2], (abf)[0][3], (bsf)[0], (bsf)[1]); \
    mma_bf16(accB,  (abf)[0][0], (abf)[0][1], (abf)[0][2], (abf)[0][3], (bsf)[2], (bsf)[3]); \
    mma_bf16(accA2, (abf)[1][0], (abf)[1][1], (abf)[1][2], (abf)[1][3], (bsf)[0], (bsf)[1]); \
    mma_bf16(accB2, (abf)[1][0], (abf)[1][1], (abf)[1][2], (abf)[1][3], (bsf)[2], (bsf)[3]); \
    mma_bf16(accA,  (asf)[0][0], (asf)[0][1], (asf)[0][2], (asf)[0][3], (bbf)[0], (bbf)[1]); \
    mma_bf16(accB,  (asf)[0][0], (asf)[0][1], (asf)[0][2], (asf)[0][3], (bbf)[2], (bbf)[3]); \
    mma_bf16(accA2, (asf)[1][0], (asf)[1][1], (asf)[1][2], (asf)[1][3], (bbf)[0], (bbf)[1]); \
    mma_bf16(accB2, (asf)[1][0], (asf)[1][1], (asf)[1][2], (asf)[1][3], (bbf)[2], (bbf)[3]); \
    mma_bf16(accA,  (abf)[0][0], (abf)[0][1], (abf)[0][2], (abf)[0][3], (bbf)[0], (bbf)[1]); \
    mma_bf16(accB,  (abf)[0][0], (abf)[0][1], (abf)[0][2], (abf)[0][3], (bbf)[2], (bbf)[3]); \
    mma_bf16(accA2, (abf)[1][0], (abf)[1][1], (abf)[1][2], (abf)[1][3], (bbf)[0], (bbf)[1]); \
    mma_bf16(accB2, (abf)[1][0], (abf)[1][1], (abf)[1][2], (abf)[1][3], (bbf)[2], (bbf)[3]); \
} while (0)

// ================= HMMA bf16x3 GEMM 128x128, single-barrier 2-stage ==========
// EPI: 0 fp32 store, 2 split-bf16 store, 3 QKV-fused (bz selects dest/format)
#define BM 128
#define BN 128
#define BK 32
#define A_ST 20
#define ASZ  (128 * A_ST)
#define BNT_ST 20
#define BNN_ST 68

template <bool NT, int EPI, bool TRUNC, bool LOWER>
__global__ __launch_bounds__(256, 2) void gemm_bf3(
    const bf16* __restrict__ Agb, const bf16* __restrict__ Ags, int lda, size_t sA,
    const bf16* __restrict__ Bgb, const bf16* __restrict__ Bgs, int ldb, size_t sB,
    float* __restrict__ Cf, float* __restrict__ Cf2,
    bf16* __restrict__ Cb, bf16* __restrict__ Cs,
    int ldc, size_t sC, int K, float alpha)
{
    const int bz = blockIdx.z;
    Agb += (size_t)bz * sA; Ags += (size_t)bz * sA;
    Bgb += (size_t)bz * sB; Bgs += (size_t)bz * sB;
    if (EPI == 2) { Cb += (size_t)bz * sC; Cs += (size_t)bz * sC; }
    else if (EPI == 0) { Cf += (size_t)bz * sC; }

    int bm, bn;
    if (LOWER) {
        int idx = blockIdx.x;
        int r = (int)((sqrtf(8.f * (float)idx + 1.f) - 1.f) * 0.5f);
        while ((r + 1) * (r + 2) / 2 <= idx) r++;
        while (r * (r + 1) / 2 > idx) r--;
        bm = r * BM;
        bn = (idx - r * (r + 1) / 2) * BN;
    } else if (TRUNC) {
        bm = (gridDim.y - 1 - blockIdx.y) * BM;
        bn = blockIdx.x * BN;
    } else {
        bm = blockIdx.y * BM;
        bn = blockIdx.x * BN;
    }

    const int tid  = threadIdx.x;
    const int wid  = tid >> 5;
    const int lane = tid & 31;
    const int g  = lane >> 2;
    const int tg = lane & 3;
    const int wm = (wid & 3) * 32;
    const int wn = (wid >> 2) * 64;

    extern __shared__ unsigned sm[];
    const unsigned smb = (unsigned)__cvta_generic_to_shared(sm);
    const int BSZ = NT ? (128 * BNT_ST) : (32 * BNN_ST);
    const int STG = 2 * ASZ + 2 * BSZ;
    const int OFF_AB = 0, OFF_AS = ASZ, OFF_BB = 2 * ASZ, OFF_BS = 2 * ASZ + BSZ;

    const int kend = TRUNC ? (bm + BM) : K;
    const int T = kend / BK;

    float acc[2][8][4];
#pragma unroll
    for (int i = 0; i < 2; i++)
#pragma unroll
        for (int j = 0; j < 8; j++)
#pragma unroll
            for (int t2 = 0; t2 < 4; t2++) acc[i][j][t2] = 0.f;

    const int a_row = (lane & 15);
    const int a_hi  = (lane >> 4) << 2;
    const int bnt_row = (lane & 7) + ((lane >> 4) & 1) * 8;
    const int bnt_hi  = ((lane >> 3) & 1) * 4;
    const int bnn_krow = (lane & 15);
    const int bnn_nhi  = ((lane >> 4) & 1) * 8;

    // prefetch tile 0
    {
        const int so = 0;
#pragma unroll
        for (int r = 0; r < 2; r++) {
            int s = tid + r * 256;
            int arow = s >> 2, aseg = s & 3;
            size_t aoff = (size_t)(bm + arow) * lda + aseg * 8;
            unsigned adst = smb + (so + OFF_AB + arow * A_ST + aseg * 4) * 4;
            cp16(adst, Agb + aoff);
            cp16(adst + ASZ * 4, Ags + aoff);
            if (NT) {
                size_t boff = (size_t)(bn + arow) * ldb + aseg * 8;
                unsigned bdst = smb + (so + OFF_BB + arow * BNT_ST + aseg * 4) * 4;
                cp16(bdst, Bgb + boff);
                cp16(bdst + BSZ * 4, Bgs + boff);
            } else {
                int krow = s >> 4, nseg = s & 15;
                size_t boff = (size_t)krow * ldb + bn + nseg * 8;
                unsigned bdst = smb + (so + OFF_BB + krow * BNN_ST + nseg * 4) * 4;
                cp16(bdst, Bgb + boff);
                cp16(bdst + BSZ * 4, Bgs + boff);
            }
        }
        cp_commit();
    }

    for (int t = 0; t < T; t++) {
        cp_wait0();
        __syncthreads();

        if (t + 1 < T) {
            const int so = ((t + 1) & 1) * STG;
            const int k0 = (t + 1) * BK;
#pragma unroll
            for (int r = 0; r < 2; r++) {
                int s = tid + r * 256;
                int arow = s >> 2, aseg = s & 3;
                size_t aoff = (size_t)(bm + arow) * lda + k0 + aseg * 8;
                unsigned adst = smb + (so + OFF_AB + arow * A_ST + aseg * 4) * 4;
                cp16(adst, Agb + aoff);
                cp16(adst + ASZ * 4, Ags + aoff);
                if (NT) {
                    size_t boff = (size_t)(bn + arow) * ldb + k0 + aseg * 8;
                    unsigned bdst = smb + (so + OFF_BB + arow * BNT_ST + aseg * 4) * 4;
                    cp16(bdst, Bgb + boff);
                    cp16(bdst + BSZ * 4, Bgs + boff);
                } else {
                    int krow = s >> 4, nseg = s & 15;
                    size_t boff = (size_t)(k0 + krow) * ldb + bn + nseg * 8;
                    unsigned bdst = smb + (so + OFF_BB + krow * BNN_ST + nseg * 4) * 4;
                    cp16(bdst, Bgb + boff);
                    cp16(bdst + BSZ * 4, Bgs + boff);
                }
            }
            cp_commit();
        }

        const int so = (t & 1) * STG;
#pragma unroll
        for (int kk = 0; kk < 2; kk++) {
            unsigned ab[2][4], as_[2][4];
#pragma unroll
            for (int mi = 0; mi < 2; mi++) {
                int idx = (wm + mi * 16 + a_row) * A_ST + kk * 8 + a_hi;
                ldsm_x4(ab[mi],  smb + (so + OFF_AB + idx) * 4);
                ldsm_x4(as_[mi], smb + (so + OFF_AS + idx) * 4);
            }
#pragma unroll
            for (int nj = 0; nj < 4; nj++) {
                unsigned bb[4], bs[4];
                if (NT) {
                    int idx = (wn + nj * 16 + bnt_row) * BNT_ST + kk * 8 + bnt_hi;
                    ldsm_x4(bb, smb + (so + OFF_BB + idx) * 4);
                    ldsm_x4(bs, smb + (so + OFF_BS + idx) * 4);
                } else {
                    int idx = (kk * 16 + bnn_krow) * BNN_ST + ((wn + nj * 16 + bnn_nhi) >> 1);
                    ldsm_x4t(bb, smb + (so + OFF_BB + idx) * 4);
                    ldsm_x4t(bs, smb + (so + OFF_BS + idx) * 4);
                }
                MMA_NJ_BLOCK(acc[0][2 * nj], acc[0][2 * nj + 1],
                             acc[1][2 * nj], acc[1][2 * nj + 1], ab, as_, bb, bs);
            }
        }
    }

    const bool split_out = (EPI == 2) || (EPI == 3 && bz == 2);
    float* fout = (EPI == 3) ? ((bz == 1) ? Cf2 : Cf) : Cf;

#pragma unroll
    for (int mi = 0; mi < 2; mi++) {
#pragma unroll
        for (int ni = 0; ni < 8; ni++) {
            int r0 = bm + wm + mi * 16 + g;
            int c0 = bn + wn + ni * 8 + tg * 2;
            float v0 = acc[mi][ni][0] * alpha;
            float v1 = acc[mi][ni][1] * alpha;
            float v2 = acc[mi][ni][2] * alpha;
            float v3 = acc[mi][ni][3] * alpha;
            if (split_out) {
                bf16 b0 = __float2bfloat16(v0), b1 = __float2bfloat16(v1);
                bf16 b2 = __float2bfloat16(v2), b3 = __float2bfloat16(v3);
                __nv_bfloat162 pb0, pb1, ps0, ps1;
                pb0.x = b0; pb0.y = b1; pb1.x = b2; pb1.y = b3;
                ps0.x = __float2bfloat16(v0 - __bfloat162float(b0));
                ps0.y = __float2bfloat16(v1 - __bfloat162float(b1));
                ps1.x = __float2bfloat16(v2 - __bfloat162float(b2));
                ps1.y = __float2bfloat16(v3 - __bfloat162float(b3));
                *(__nv_bfloat162*)(Cb + (size_t)r0 * ldc + c0)       = pb0;
                *(__nv_bfloat162*)(Cb + (size_t)(r0 + 8) * ldc + c0) = pb1;
                *(__nv_bfloat162*)(Cs + (size_t)r0 * ldc + c0)       = ps0;
                *(__nv_bfloat162*)(Cs + (size_t)(r0 + 8) * ldc + c0) = ps1;
            } else {
                *(float2*)(fout + (size_t)r0 * ldc + c0)       = make_float2(v0, v1);
                *(float2*)(fout + (size_t)(r0 + 8) * ldc + c0) = make_float2(v2, v3);
            }
        }
    }
}

// ---------------- split fp32 -> bf16 big/small --------------------------------
__device__ __forceinline__ void split4(const float4 v, bf16* xb, bf16* xs, size_t i)
{
    bf16 b0 = __float2bfloat16(v.x), b1 = __float2bfloat16(v.y);
    bf16 b2 = __float2bfloat16(v.z), b3 = __float2bfloat16(v.w);
    __nv_bfloat162 pb0, pb1, ps0, ps1;
    pb0.x = b0; pb0.y = b1; pb1.x = b2; pb1.y = b3;
    ps0.x = __float2bfloat16(v.x - __bfloat162float(b0));
    ps0.y = __float2bfloat16(v.y - __bfloat162float(b1));
    ps1.x = __float2bfloat16(v.z - __bfloat162float(b2));
    ps1.y = __float2bfloat16(v.w - __bfloat162float(b3));
    *(__nv_bfloat162*)(xb + i)     = pb0;
    *(__nv_bfloat162*)(xb + i + 2) = pb1;
    *(__nv_bfloat162*)(xs + i)     = ps0;
    *(__nv_bfloat162*)(xs + i + 2) = ps1;
}

__global__ void split_kernel(const float* __restrict__ x,
                             bf16* __restrict__ xb, bf16* __restrict__ xs)
{
    size_t i = ((size_t)blockIdx.x * 256 + threadIdx.x) * 8;
    float4 v0 = *(const float4*)(x + i);
    float4 v1 = *(const float4*)(x + i + 4);
    split4(v0, xb, xs, i);
    split4(v1, xb, xs, i + 4);
}

__global__ void splitw_kernel(const float* __restrict__ W0, const float* __restrict__ W1,
                              const float* __restrict__ W2, const float* __restrict__ W3,
                              bf16* __restrict__ xb, bf16* __restrict__ xs)
{
    int w = blockIdx.y;
    const float* x = (w == 0) ? W0 : (w == 1) ? W1 : (w == 2) ? W2 : W3;
    size_t base = (size_t)w * HID * HID;
    size_t i = ((size_t)blockIdx.x * 256 + threadIdx.x) * 8;
    float4 v0 = *(const float4*)(x + i);
    float4 v1 = *(const float4*)(x + i + 4);
    split4(v0, xb + base, xs + base, i);
    split4(v1, xb + base, xs + base, i + 4);
}

// ---------------- MsPoE rotary -> split bf16 ----------------------------------
__global__ void rope_split_kernel(const float* __restrict__ q, const float* __restrict__ k,
                                  const int* __restrict__ pos_ids,
                                  bf16* __restrict__ qb, bf16* __restrict__ qs,
                                  bf16* __restrict__ kb, bf16* __restrict__ ks)
{
    int i = blockIdx.x * blockDim.x + threadIdx.x;
    int d = i & 63;
    int h = (i >> 6) & 31;
    int s = i >> 11;
    float ratio = 1.2f + (0.6f / 31.0f) * (float)h;
    float t = (float)pos_ids[s] / ratio;
    float inv_freq = exp2f(-(float)d * (13.287712379549449f / 64.0f));
    float f = t * inv_freq;
    float c, sn;
    sincosf(f, &sn, &c);
    size_t base = (size_t)s * HID + h * HD + d;

    float x1 = q[base], x2 = q[base + 64];
    float y0 = x1 * c - x2 * sn;
    float y1 = x2 * c + x1 * sn;
    bf16 t0 = __float2bfloat16(y0);
    bf16 t1 = __float2bfloat16(y1);
    qb[base] = t0;
    qs[base] = __float2bfloat16(y0 - __bfloat162float(t0));
    qb[base + 64] = t1;
    qs[base + 64] = __float2bfloat16(y1 - __bfloat162float(t1));

    x1 = k[base]; x2 = k[base + 64];
    y0 = x1 * c - x2 * sn;
    y1 = x2 * c + x1 * sn;
    t0 = __float2bfloat16(y0);
    t1 = __float2bfloat16(y1);
    kb[base] = t0;
    ks[base] = __float2bfloat16(y0 - __bfloat162float(t0));
    kb[base + 64] = t1;
    ks[base + 64] = __float2bfloat16(y1 - __bfloat162float(t1));
}

// ---------------- probs1: in-place softmax over k<=q ---------------------------
__global__ void probs1_kernel(float* __restrict__ scores)
{
    int q = blockIdx.x, h = blockIdx.y;
    float* row = scores + ((size_t)h * S + q) * S;
    __shared__ float red[256];
    int tid = threadIdx.x;

    float v[8];
    float m = -INFINITY;
#pragma unroll
    for (int j = 0; j < 8; j++) {
        int k = tid + j * 256;
        v[j] = (k <= q) ? row[k] : -INFINITY;
        m = fmaxf(m, v[j]);
    }
    red[tid] = m;
    __syncthreads();
    for (int st = 128; st; st >>= 1) {
        if (tid < st) red[tid] = fmaxf(red[tid], red[tid + st]);
        __syncthreads();
    }
    m = red[0];
    __syncthreads();

    float sum = 0.f;
#pragma unroll
    for (int j = 0; j < 8; j++) {
        v[j] = (v[j] > -INFINITY) ? __expf(v[j] - m) : 0.f;
        sum += v[j];
    }
    red[tid] = sum;
    __syncthreads();
    for (int st = 128; st; st >>= 1) {
        if (tid < st) red[tid] += red[tid + st];
        __syncthreads();
    }
    float inv = 1.0f / red[0];
#pragma unroll
    for (int j = 0; j < 8; j++) {
        int k = tid + j * 256;
        if (k <= q) row[k] = v[j] * inv;
    }
}

// ---------------- hh partial sums over q-chunks --------------------------------
__global__ void hh_part_kernel(const float* __restrict__ p1, float* __restrict__ part)
{
    int kb = blockIdx.x, qc = blockIdx.y, h = blockIdx.z;
    if (qc < kb) return;
    int k = kb * 256 + threadIdx.x;
    const float* base = p1 + (size_t)h * S * S;
    int q0 = qc * 256;
    float acc = 0.f;
    for (int q = q0; q < q0 + 256; q++) {
        if (q >= k) acc += base[(size_t)q * S + k];
    }
    part[((size_t)qc * NH + h) * S + k] = acc;
}

__global__ void hh_reduce_kernel(const float* __restrict__ part, float* __restrict__ hh)
{
    int h = blockIdx.y;
    int k = blockIdx.x * 256 + threadIdx.x;
    int kb = k >> 8;
    float acc = 0.f;
    for (int qc = kb; qc < 8; qc++)
        acc += part[((size_t)qc * NH + h) * S + k];
    hh[h * S + k] = acc;
}

// ---------------- top-204 via histogram pruning + warp selection ----------------
__global__ void topk_mask_kernel(const float* __restrict__ hh, float* __restrict__ mask)
{
    int h = blockIdx.x, tid = threadIdx.x;
    __shared__ float cv[SEL];
    __shared__ int   ci[SEL];
    __shared__ unsigned hist[2048];
    __shared__ int cand_n, thrbin;

    for (int i = tid; i < 2048; i += 256) hist[i] = 0;
    for (int k = tid; k < S; k += 256) mask[h * S + k] = (k >= SEL) ? 0.f : NEGV;
    if (tid == 0) cand_n = 0;
    __syncthreads();

    // histogram on top 11 bits of positive-float bit pattern (monotonic)
    for (int i = tid; i < SEL; i += 256) {
        unsigned b = __float_as_uint(hh[h * S + i]);
        atomicAdd(&hist[b >> 21], 1u);
    }
    __syncthreads();

    if (tid == 0) {
        unsigned c = 0;
        int b = 2047;
        for (; b > 0; b--) {
            c += hist[b];
            if (c >= HHSZ) break;
        }
        thrbin = b;
    }
    __syncthreads();
    int tb = thrbin;

    // compact candidates (bin >= thrbin); contains all of the true top-204
    for (int i = tid; i < SEL; i += 256) {
        float v = hh[h * S + i];
        if ((int)(__float_as_uint(v) >> 21) >= tb) {
            int p = atomicAdd(&cand_n, 1);
            cv[p] = v;
            ci[p] = i;
        }
    }
    __syncthreads();
    int n = cand_n;

    // warp 0 performs 204 selections ordered by (value desc, original index asc)
    if (tid < 32) {
        for (int it = 0; it < HHSZ; it++) {
            float bm = -INFINITY;
            int bi = 1 << 30;
            for (int j = tid; j < n; j += 32) {
                float v = cv[j];
                int oi = ci[j];
                if (v > bm || (v == bm && oi < bi)) { bm = v; bi = oi; }
            }
#pragma unroll
            for (int off = 16; off; off >>= 1) {
                float ov = __shfl_down_sync(0xffffffffu, bm, off);
                int   oi = __shfl_down_sync(0xffffffffu, bi, off);
                if (ov > bm || (ov == bm && oi < bi)) { bm = ov; bi = oi; }
            }
            bi = __shfl_sync(0xffffffffu, bi, 0);
            if (tid == 0) mask[h * S + bi] = 0.f;
            for (int j = tid; j < n; j += 32)
                if (ci[j] == bi) cv[j] = -INFINITY;
            __syncwarp();
        }
    }
}

// ---------------- collect kept indices (sorted ascending) ----------------------
__global__ void collect_idx_kernel(const float* __restrict__ mask, int* __restrict__ idx)
{
    int h = blockIdx.x, tid = threadIdx.x;
    __shared__ int cnt[256];
    int local[8];
    int c = 0;
#pragma unroll
    for (int i = 0; i < 8; i++) {
        int k = tid * 8 + i;
        if (mask[h * S + k] == 0.f) local[c++] = k;
    }
    cnt[tid] = c;
    __syncthreads();
    for (int off = 1; off < 256; off <<= 1) {
        int v = (tid >= off) ? cnt[tid - off] : 0;
        __syncthreads();
        cnt[tid] += v;
        __syncthreads();
    }
    int base = cnt[tid] - c;
    for (int j = 0; j < c; j++) idx[h * NKP + base + j] = local[j];
    if (tid < NKP - NKEEP) idx[h * NKP + NKEEP + tid] = -1;
}

// ---------------- gather compacted V -------------------------------------------
__global__ void vc_gather_kernel(const int* __restrict__ idx,
                                 const bf16* __restrict__ vb, const bf16* __restrict__ vs,
                                 bf16* __restrict__ vcb, bf16* __restrict__ vcs)
{
    int j = blockIdx.x, h = blockIdx.y, d = threadIdx.x;
    int i = idx[h * NKP + j];
    size_t o = ((size_t)h * NKP + j) * HD + d;
    bf16 z = __float2bfloat16(0.f);
    vcb[o] = (i >= 0) ? vb[(size_t)i * HID + h * HD + d] : z;
    vcs[o] = (i >= 0) ? vs[(size_t)i * HID + h * HD + d] : z;
}

// ---------------- softmax2: renormalize + compact kept columns ------------------
__global__ void softmax2_compact_kernel(const float* __restrict__ p1,
                                        const float* __restrict__ mask,
                                        const int* __restrict__ idx,
                                        bf16* __restrict__ pcb, bf16* __restrict__ pcs,
                                        float* __restrict__ pdiag)
{
    int q = blockIdx.x, h = blockIdx.y, tid = threadIdx.x;
    const float* row = p1 + ((size_t)h * S + q) * S;
    __shared__ int sidx[NKP];
    __shared__ float red[256];
    for (int j = tid; j < NKP; j += 256) sidx[j] = idx[h * NKP + j];
    __syncthreads();

    float v[2];
    float sum = 0.f;
#pragma unroll
    for (int r = 0; r < 2; r++) {
        int j = tid + r * 256;
        float p = 0.f;
        if (j < NKP) {
            int ij = sidx[j];
            if (ij >= 0 && ij <= q) p = row[ij];
        }
        v[r] = p;
        sum += p;
    }
    bool kept_q = (mask[h * S + q] == 0.f);
    float pd = kept_q ? 0.f : row[q];

    red[tid] = sum;
    __syncthreads();
    for (int st = 128; st; st >>= 1) {
        if (tid < st) red[tid] += red[tid + st];
        __syncthreads();
    }
    float inv = 1.0f / (red[0] + pd);

    size_t off = ((size_t)h * S + q) * NKP;
#pragma unroll
    for (int r = 0; r < 2; r++) {
        int j = tid + r * 256;
        if (j < NKP) {
            float val = v[r] * inv;
            bf16 b = __float2bfloat16(val);
            pcb[off + j] = b;
            pcs[off + j] = __float2bfloat16(val - __bfloat162float(b));
        }
    }
    if (tid == 0) pdiag[h * S + q] = kept_q ? 0.f : pd * inv;
}

// ---------------- add diagonal term + split attn to bf16 ------------------------
__global__ void diag_split_kernel(const float* __restrict__ attn,
                                  const float* __restrict__ pdiag,
                                  const bf16* __restrict__ vb, const bf16* __restrict__ vs,
                                  bf16* __restrict__ ab, bf16* __restrict__ as_)
{
    size_t e = ((size_t)blockIdx.x * 256 + threadIdx.x) * 4;
    int q = (int)(e / HID);
    int col = (int)(e % HID);
    int h = col >> 7;
    float pdv = pdiag[h * S + q];
    float4 a = *(const float4*)(attn + e);
    float4 o;
    o.x = a.x + pdv * (__bfloat162float(vb[e + 0]) + __bfloat162float(vs[e + 0]));
    o.y = a.y + pdv * (__bfloat162float(vb[e + 1]) + __bfloat162float(vs[e + 1]));
    o.z = a.z + pdv * (__bfloat162float(vb[e + 2]) + __bfloat162float(vs[e + 2]));
    o.w = a.w + pdv * (__bfloat162float(vb[e + 3]) + __bfloat162float(vs[e + 3]));
    split4(o, ab, as_, e);
}

// ---------------- launch --------------------------------------------------------
extern "C" void kernel_launch(void* const* d_in, const int* in_sizes, int n_in,
                              void* d_out, int out_size)
{
    const float* hs = (const float*)d_in[0];
    const float* W0 = (const float*)d_in[1];
    const float* W1 = (const float*)d_in[2];
    const float* W2 = (const float*)d_in[3];
    const float* W3 = (const float*)d_in[4];
    const int* pos = (const int*)d_in[5];
    float* out = (float*)d_out;

    float *q, *k, *scores, *hh, *hhp, *mask, *pdiag;
    int* idx;
    bf16 *hsb, *hss, *wb, *ws, *qb, *qs, *kb, *ks, *vb, *vs;
    bf16 *pcb, *pcs, *vcb, *vcs, *ab, *as;
    cudaGetSymbolAddress((void**)&q, g_q);
    cudaGetSymbolAddress((void**)&k, g_k);
    cudaGetSymbolAddress((void**)&scores, g_scores);
    cudaGetSymbolAddress((void**)&hh, g_hh);
    cudaGetSymbolAddress((void**)&hhp, g_hhpart);
    cudaGetSymbolAddress((void**)&mask, g_mask);
    cudaGetSymbolAddress((void**)&pdiag, g_pdiag);
    cudaGetSymbolAddress((void**)&idx, g_idx);
    cudaGetSymbolAddress((void**)&hsb, g_hs_b);
    cudaGetSymbolAddress((void**)&hss, g_hs_s);
    cudaGetSymbolAddress((void**)&wb, g_w_b);
    cudaGetSymbolAddress((void**)&ws, g_w_s);
    cudaGetSymbolAddress((void**)&qb, g_qb);
    cudaGetSymbolAddress((void**)&qs, g_qs);
    cudaGetSymbolAddress((void**)&kb, g_kb);
    cudaGetSymbolAddress((void**)&ks, g_ks);
    cudaGetSymbolAddress((void**)&vb, g_vb);
    cudaGetSymbolAddress((void**)&vs, g_vs);
    cudaGetSymbolAddress((void**)&pcb, g_pcb);
    cudaGetSymbolAddress((void**)&pcs, g_pcs);
    cudaGetSymbolAddress((void**)&vcb, g_vcb);
    cudaGetSymbolAddress((void**)&vcs, g_vcs);
    cudaGetSymbolAddress((void**)&ab, g_ab);
    cudaGetSymbolAddress((void**)&as, g_as);

    const int SM_NT = (2 * (2 * ASZ + 2 * 128 * BNT_ST)) * 4;
    const int SM_NN = (2 * (2 * ASZ + 2 * 32 * BNN_ST)) * 4;
    cudaFuncSetAttribute(gemm_bf3<true, 3, false, false>, cudaFuncAttributeMaxDynamicSharedMemorySize, SM_NT);
    cudaFuncSetAttribute(gemm_bf3<true, 0, false, false>, cudaFuncAttributeMaxDynamicSharedMemorySize, SM_NT);
    cudaFuncSetAttribute(gemm_bf3<true, 0, false, true>,  cudaFuncAttributeMaxDynamicSharedMemorySize, SM_NT);
    cudaFuncSetAttribute(gemm_bf3<false, 0, false, false>, cudaFuncAttributeMaxDynamicSharedMemorySize, SM_NN);

    split_kernel<<<(S * HID) / 2048, 256>>>(hs, hsb, hss);
    splitw_kernel<<<dim3((HID * HID) / 2048, 4), 256>>>(W0, W1, W2, W3, wb, ws);

    // fused Q/K/V projections
    dim3 gqkv(HID / BN, S / BM, 3);
    gemm_bf3<true, 3, false, false><<<gqkv, 256, SM_NT>>>(
        hsb, hss, HID, 0, wb, ws, HID, (size_t)HID * HID,
        q, k, vb, vs, HID, 0, HID, 1.f);

    rope_split_kernel<<<(S * NH * 64) / 256, 256>>>(q, k, pos, qb, qs, kb, ks);

    // QK^T lower-triangle tiles only
    dim3 gs(136, 1, NH);
    gemm_bf3<true, 0, false, true><<<gs, 256, SM_NT>>>(
        qb, qs, HID, (size_t)HD, kb, ks, HID, (size_t)HD,
        scores, (float*)0, (bf16*)0, (bf16*)0, S, (size_t)S * S, HD, 0.08838834764831845f);

    probs1_kernel<<<dim3(S, NH), 256>>>(scores);
    hh_part_kernel<<<dim3(8, 8, NH), 256>>>(scores, hhp);
    hh_reduce_kernel<<<dim3(8, NH), 256>>>(hhp, hh);
    topk_mask_kernel<<<NH, 256>>>(hh, mask);

    // sparse PV path
    collect_idx_kernel<<<NH, 256>>>(mask, idx);
    vc_gather_kernel<<<dim3(NKP, NH), 128>>>(idx, vb, vs, vcb, vcs);
    softmax2_compact_kernel<<<dim3(S, NH), 256>>>(scores, mask, idx, pcb, pcs, pdiag);

    // PV: attn_fp32 = Pc @ Vc (uniform K=416)
    dim3 gpv(1, S / BM, NH);
    gemm_bf3<false, 0, false, false><<<gpv, 256, SM_NN>>>(
        pcb, pcs, NKP, (size_t)S * NKP, vcb, vcs, HD, (size_t)NKP * HD,
        q, (float*)0, (bf16*)0, (bf16*)0, HID, (size_t)HD, NKP, 1.f);

    diag_split_kernel<<<(S * HID) / 1024, 256>>>(q, pdiag, vb, vs, ab, as);

    // O projection
    gemm_bf3<true, 0, false, false><<<dim3(HID / BN, S / BM, 1), 256, SM_NT>>>(
        ab, as, HID, 0, wb + 3 * (size_t)HID * HID, ws + 3 * (size_t)HID * HID, HID, 0,
        out, (float*)0, (bf16*)0, (bf16*)0, HID, 0, HID, 1.f);
}